// round 2
// baseline (speedup 1.0000x reference)
#include <cuda_runtime.h>
#include <cuda_bf16.h>
#include <math.h>

#define SEQ   1024
#define HID   4096
#define NH    32
#define HD    128
#define INTER 11008
#define NL    2

// ---------------- scratch (device globals; no allocations allowed) ----------
__device__ float g_y[SEQ * HID];                 // rmsnorm output / attn-out buffer
__device__ float g_o[SEQ * HID];                 // proj outputs before residual add
__device__ float g_qkv[SEQ * 3 * HID];
__device__ float g_q[NH * SEQ * HD];
__device__ float g_k[NH * SEQ * HD];
__device__ float g_vT[NH * HD * SEQ];
__device__ float g_sc[(size_t)NH * SEQ * SEQ];   // attention scores / probs (134 MB)
__device__ float g_gate[SEQ * INTER];
__device__ float g_up[SEQ * INTER];

// ---------------- RMSNorm: one block per row ----------------
__global__ void __launch_bounds__(256) rmsnorm_kernel(
    const float* __restrict__ x, const float* __restrict__ w, float* __restrict__ y)
{
    int s = blockIdx.x;
    const float* row = x + (long long)s * HID;
    float* out = y + (long long)s * HID;
    int tid = threadIdx.x;

    float ss = 0.f;
    for (int i = tid; i < HID; i += 256) { float v = row[i]; ss += v * v; }
    __shared__ float red[256];
    red[tid] = ss; __syncthreads();
    for (int st = 128; st > 0; st >>= 1) { if (tid < st) red[tid] += red[tid + st]; __syncthreads(); }
    float inv = rsqrtf(red[0] / (float)HID + 1e-6f);
    for (int i = tid; i < HID; i += 256) out[i] = row[i] * inv * w[i];
}

// ---------------- generic batched NT GEMM: C[m,n] = sum_k A[m,k]*B[n,k] -----
#define BM 128
#define BN 128
#define BKK 8
#define TM 8
#define TN 8

__global__ void __launch_bounds__(256) gemm_nt(
    const float* __restrict__ A, const float* __restrict__ B, float* __restrict__ C,
    int M, int N, int K, int lda, int ldb, int ldc,
    long long sA, long long sB, long long sC)
{
    int batch = blockIdx.z;
    A += batch * sA;  B += batch * sB;  C += batch * sC;

    int bm = blockIdx.y * BM;
    int bn = blockIdx.x * BN;

    __shared__ float As[BKK][BM];
    __shared__ float Bs[BKK][BN];

    int tid = threadIdx.x;
    int aRow = tid >> 1;            // 0..127
    int aCol = (tid & 1) * 4;       // 0 or 4
    int tr = (tid >> 4) * TM;       // 0..120
    int tc = (tid & 15) * TN;       // 0..120

    const float* Aptr = A + (long long)bm * lda;
    const float* Bptr = B + (long long)bn * ldb;

    float acc[TM][TN];
    #pragma unroll
    for (int i = 0; i < TM; i++)
        #pragma unroll
        for (int j = 0; j < TN; j++) acc[i][j] = 0.f;

    for (int k0 = 0; k0 < K; k0 += BKK) {
        float4 av = *reinterpret_cast<const float4*>(Aptr + (long long)aRow * lda + k0 + aCol);
        float4 bv = *reinterpret_cast<const float4*>(Bptr + (long long)aRow * ldb + k0 + aCol);
        As[aCol + 0][aRow] = av.x; As[aCol + 1][aRow] = av.y;
        As[aCol + 2][aRow] = av.z; As[aCol + 3][aRow] = av.w;
        Bs[aCol + 0][aRow] = bv.x; Bs[aCol + 1][aRow] = bv.y;
        Bs[aCol + 2][aRow] = bv.z; Bs[aCol + 3][aRow] = bv.w;
        __syncthreads();

        #pragma unroll
        for (int k = 0; k < BKK; k++) {
            float ar[TM], br[TN];
            float4 a0 = *reinterpret_cast<const float4*>(&As[k][tr]);
            float4 a1 = *reinterpret_cast<const float4*>(&As[k][tr + 4]);
            float4 b0 = *reinterpret_cast<const float4*>(&Bs[k][tc]);
            float4 b1 = *reinterpret_cast<const float4*>(&Bs[k][tc + 4]);
            ar[0]=a0.x; ar[1]=a0.y; ar[2]=a0.z; ar[3]=a0.w;
            ar[4]=a1.x; ar[5]=a1.y; ar[6]=a1.z; ar[7]=a1.w;
            br[0]=b0.x; br[1]=b0.y; br[2]=b0.z; br[3]=b0.w;
            br[4]=b1.x; br[5]=b1.y; br[6]=b1.z; br[7]=b1.w;
            #pragma unroll
            for (int i = 0; i < TM; i++)
                #pragma unroll
                for (int j = 0; j < TN; j++) acc[i][j] += ar[i] * br[j];
        }
        __syncthreads();
    }

    #pragma unroll
    for (int i = 0; i < TM; i++) {
        float* crow = C + (long long)(bm + tr + i) * ldc + bn + tc;
        #pragma unroll
        for (int j = 0; j < TN; j++) crow[j] = acc[i][j];
    }
}

// ---------------- qkv split + RoPE + V transpose ----------------
__global__ void __launch_bounds__(256) rope_split_kernel(
    const float* __restrict__ qkv,
    const float* __restrict__ cosT, const float* __restrict__ sinT,
    const int* __restrict__ pos_ids,
    float* __restrict__ q, float* __restrict__ k, float* __restrict__ vT)
{
    int s = blockIdx.x;
    int pos = pos_ids[s];
    if (pos < 0) pos = 0;
    if (pos >= SEQ) pos = SEQ - 1;
    const float* c = cosT + (long long)pos * HD;
    const float* sn = sinT + (long long)pos * HD;
    const float* row = qkv + (long long)s * (3 * HID);

    for (int idx = threadIdx.x; idx < HID; idx += 256) {
        int h = idx >> 7;
        int d = idx & 127;
        float qv = row[idx];
        float kv = row[HID + idx];
        float vv = row[2 * HID + idx];
        float qo = (d < 64) ? -row[idx + 64] : row[idx - 64];
        float ko = (d < 64) ? -row[HID + idx + 64] : row[HID + idx - 64];
        float cd = c[d], sd = sn[d];
        long long qi = ((long long)h * SEQ + s) * HD + d;
        q[qi] = qv * cd + qo * sd;
        k[qi] = kv * cd + ko * sd;
        vT[((long long)h * HD + d) * SEQ + s] = vv;
    }
}

// ---------------- causal softmax (in place, with 1/sqrt(hd) scale) ----------
__global__ void __launch_bounds__(256) softmax_causal_kernel(float* __restrict__ scores)
{
    int qrow = blockIdx.x;
    int head = blockIdx.y;
    float* row = scores + ((long long)head * SEQ + qrow) * SEQ;
    int n = qrow + 1;
    int tid = threadIdx.x;
    const float scale = 0.088388347648318447f;  // 1/sqrt(128)

    __shared__ float red[256];

    float m = -3.4e38f;
    for (int i = tid; i < n; i += 256) m = fmaxf(m, row[i] * scale);
    red[tid] = m; __syncthreads();
    for (int st = 128; st > 0; st >>= 1) { if (tid < st) red[tid] = fmaxf(red[tid], red[tid + st]); __syncthreads(); }
    m = red[0]; __syncthreads();

    float sum = 0.f;
    for (int i = tid; i < n; i += 256) {
        float e = expf(row[i] * scale - m);
        row[i] = e;
        sum += e;
    }
    red[tid] = sum; __syncthreads();
    for (int st = 128; st > 0; st >>= 1) { if (tid < st) red[tid] += red[tid + st]; __syncthreads(); }
    float inv = 1.f / red[0];

    for (int i = tid; i < n; i += 256) row[i] *= inv;
    for (int i = n + tid; i < SEQ; i += 256) row[i] = 0.f;
}

// ---------------- elementwise ----------------
__global__ void __launch_bounds__(256) add_kernel(float* __restrict__ a, const float* __restrict__ b, int n)
{
    int i = blockIdx.x * 256 + threadIdx.x;
    if (i < n) a[i] += b[i];
}

__global__ void __launch_bounds__(256) silu_mul_kernel(float* __restrict__ g, const float* __restrict__ u, int n)
{
    int i = blockIdx.x * 256 + threadIdx.x;
    if (i < n) {
        float x = g[i];
        g[i] = x / (1.f + expf(-x)) * u[i];
    }
}

// ---------------- orchestration ----------------
extern "C" void kernel_launch(void* const* d_in, const int* in_sizes, int n_in,
                              void* d_out, int out_size)
{
    const float* x      = (const float*)d_in[0];
    const int*   pos    = (const int*)d_in[1];      // int32 (JAX x64 disabled)
    const float* qkv_w  = (const float*)d_in[2];
    const float* o_w    = (const float*)d_in[3];
    const float* gate_w = (const float*)d_in[4];
    const float* up_w   = (const float*)d_in[5];
    const float* down_w = (const float*)d_in[6];
    const float* ln1_w  = (const float*)d_in[7];
    const float* ln2_w  = (const float*)d_in[8];
    const float* cosT   = (const float*)d_in[9];
    const float* sinT   = (const float*)d_in[10];
    float* h = (float*)d_out;

    float *y, *o, *qkv, *q, *k, *vT, *sc, *gate, *up;
    cudaGetSymbolAddress((void**)&y, g_y);
    cudaGetSymbolAddress((void**)&o, g_o);
    cudaGetSymbolAddress((void**)&qkv, g_qkv);
    cudaGetSymbolAddress((void**)&q, g_q);
    cudaGetSymbolAddress((void**)&k, g_k);
    cudaGetSymbolAddress((void**)&vT, g_vT);
    cudaGetSymbolAddress((void**)&sc, g_sc);
    cudaGetSymbolAddress((void**)&gate, g_gate);
    cudaGetSymbolAddress((void**)&up, g_up);

    cudaMemcpyAsync(h, x, sizeof(float) * SEQ * HID, cudaMemcpyDeviceToDevice, 0);

    const int nEl = SEQ * HID;
    const int nElI = SEQ * INTER;

    for (int L = 0; L < NL; L++) {
        const float* qw = qkv_w  + (size_t)L * 3 * HID * HID;
        const float* ow = o_w    + (size_t)L * HID * HID;
        const float* gw = gate_w + (size_t)L * INTER * HID;
        const float* uw = up_w   + (size_t)L * INTER * HID;
        const float* dw = down_w + (size_t)L * HID * INTER;

        // ---- attention block ----
        rmsnorm_kernel<<<SEQ, 256>>>(h, ln1_w + (size_t)L * HID, y);

        gemm_nt<<<dim3(3 * HID / BN, SEQ / BM, 1), 256>>>(
            y, qw, qkv, SEQ, 3 * HID, HID, HID, HID, 3 * HID, 0, 0, 0);

        rope_split_kernel<<<SEQ, 256>>>(qkv, cosT, sinT, pos, q, k, vT);

        // scores[h] = q[h] @ k[h]^T  : M=S, N=S, K=HD
        gemm_nt<<<dim3(SEQ / BN, SEQ / BM, NH), 256>>>(
            q, k, sc, SEQ, SEQ, HD, HD, HD, SEQ,
            (long long)SEQ * HD, (long long)SEQ * HD, (long long)SEQ * SEQ);

        softmax_causal_kernel<<<dim3(SEQ, NH), 256>>>(sc);

        // attnout[s, h*128+d] = probs[h] @ vT[h]^T : M=S, N=HD, K=S ; C strided into [S, HID]
        gemm_nt<<<dim3(HD / BN, SEQ / BM, NH), 256>>>(
            sc, vT, y, SEQ, HD, SEQ, SEQ, SEQ, HID,
            (long long)SEQ * SEQ, (long long)HD * SEQ, (long long)HD);

        gemm_nt<<<dim3(HID / BN, SEQ / BM, 1), 256>>>(
            y, ow, o, SEQ, HID, HID, HID, HID, HID, 0, 0, 0);

        add_kernel<<<nEl / 256, 256>>>(h, o, nEl);

        // ---- MLP block ----
        rmsnorm_kernel<<<SEQ, 256>>>(h, ln2_w + (size_t)L * HID, y);

        gemm_nt<<<dim3(INTER / BN, SEQ / BM, 1), 256>>>(
            y, gw, gate, SEQ, INTER, HID, HID, HID, INTER, 0, 0, 0);
        gemm_nt<<<dim3(INTER / BN, SEQ / BM, 1), 256>>>(
            y, uw, up, SEQ, INTER, HID, HID, HID, INTER, 0, 0, 0);

        silu_mul_kernel<<<nElI / 256, 256>>>(gate, up, nElI);

        gemm_nt<<<dim3(HID / BN, SEQ / BM, 1), 256>>>(
            gate, dw, o, SEQ, HID, INTER, INTER, INTER, HID, 0, 0, 0);

        add_kernel<<<nEl / 256, 256>>>(h, o, nEl);
    }
}

// round 4
// speedup vs baseline: 2.1688x; 2.1688x over previous
#include <cuda_runtime.h>
#include <cuda_bf16.h>
#include <math.h>
#include <stdint.h>

#define SEQ   1024
#define HID   4096
#define NH    32
#define HD    128
#define INTER 11008
#define NL    2

// ---------------- scratch (device globals; no allocations allowed) ----------
__device__ float g_y[SEQ * HID];
__device__ float g_o[SEQ * HID];
__device__ float g_qkv[SEQ * 3 * HID];
__device__ float g_q[NH * SEQ * HD];
__device__ float g_k[NH * SEQ * HD];
__device__ float g_vT[NH * HD * SEQ];
__device__ float g_sc[(size_t)NH * SEQ * SEQ];
__device__ float g_gate[SEQ * INTER];
__device__ float g_up[SEQ * INTER];

// ======================= helpers ==============================
__device__ __forceinline__ uint32_t smem_u32(const void* p) {
    uint32_t a;
    asm("{ .reg .u64 t; cvta.to.shared.u64 t, %1; cvt.u32.u64 %0, t; }" : "=r"(a) : "l"(p));
    return a;
}

__device__ __forceinline__ void ldsm_x4(uint32_t& r0, uint32_t& r1, uint32_t& r2, uint32_t& r3, uint32_t addr) {
    asm volatile("ldmatrix.sync.aligned.m8n8.x4.shared.b16 {%0,%1,%2,%3}, [%4];"
                 : "=r"(r0), "=r"(r1), "=r"(r2), "=r"(r3) : "r"(addr));
}

__device__ __forceinline__ void mma_bf16(float* c, const uint32_t* a, uint32_t b0, uint32_t b1) {
    asm volatile(
        "mma.sync.aligned.m16n8k16.row.col.f32.bf16.bf16.f32 "
        "{%0,%1,%2,%3}, {%4,%5,%6,%7}, {%8,%9}, {%0,%1,%2,%3};"
        : "+f"(c[0]), "+f"(c[1]), "+f"(c[2]), "+f"(c[3])
        : "r"(a[0]), "r"(a[1]), "r"(a[2]), "r"(a[3]), "r"(b0), "r"(b1));
}

__device__ __forceinline__ uint32_t f2bf2(float x, float y) {
    __nv_bfloat162 h = __floats2bfloat162_rn(x, y);
    return *reinterpret_cast<uint32_t*>(&h);
}

// ======================= bf16-split-3 tensor GEMM ===========================
// C[m,n] = sum_k A[m,k]*B[n,k]  (fp32 io; bf16 split: hi*hi + lo*hi + hi*lo)
// K' = 3*32 = 96 bf16 per 32-fp32 chunk:
//   A' sections [hi | lo | hi], B' sections [hi | hi | lo]
// Requires M%128==0, N%128==0, K%32==0, lda/ldb %4==0.
#define ROWB  208                    // padded row stride bytes (104 bf16)
#define ASZ   (128 * ROWB)           // 26624 B per operand tile
#define STG   (2 * ASZ)              // 53248 B per stage
#define SM_TOTAL (2 * STG)           // 106496 B (double buffer)

__global__ void __launch_bounds__(256, 1)
gemm_nt_tc(const float* __restrict__ A, const float* __restrict__ B,
           float* __restrict__ C, int K, int lda, int ldb, int ldc,
           long long sA, long long sB, long long sC)
{
    extern __shared__ char smem[];
    const int tid = threadIdx.x;
    const int lane = tid & 31;
    const int wid = tid >> 5;
    const int wm = wid >> 2;          // 0..1
    const int wn = wid & 3;           // 0..3

    A += (long long)blockIdx.z * sA;
    B += (long long)blockIdx.z * sB;
    C += (long long)blockIdx.z * sC;
    const int bm = blockIdx.y * 128;
    const int bn = blockIdx.x * 128;

    const uint32_t sb = smem_u32(smem);

    // ldmatrix base addresses (within stage 0)
    const uint32_t aAddr = sb + (uint32_t)(wm * 64 + (lane & 15)) * ROWB + (uint32_t)(lane >> 4) * 16;
    const uint32_t bAddr = sb + ASZ
        + (uint32_t)(wn * 32 + (((lane >> 4) << 3) | (lane & 7))) * ROWB
        + (uint32_t)((lane >> 3) & 1) * 16;

    // global load mapping: each thread loads 16 floats of A and of B per chunk
    const int lrow = tid >> 1;                 // 0..127
    const int lcol = (tid & 1) * 16;           // 0 or 16
    const float* Arow = A + (long long)(bm + lrow) * lda;
    const float* Brow = B + (long long)(bn + lrow) * ldb;

    float acc[4][4][4];
    #pragma unroll
    for (int mt = 0; mt < 4; mt++)
        #pragma unroll
        for (int nt = 0; nt < 4; nt++)
            #pragma unroll
            for (int i = 0; i < 4; i++) acc[mt][nt][i] = 0.f;

    float4 ra[4], rb[4];

    // ---- prologue: load chunk 0, convert+store to stage 0 ----
    #pragma unroll
    for (int v = 0; v < 4; v++) {
        ra[v] = *reinterpret_cast<const float4*>(Arow + lcol + 4 * v);
        rb[v] = *reinterpret_cast<const float4*>(Brow + lcol + 4 * v);
    }
    {
        char* base = smem;
        const uint32_t rowoff = (uint32_t)lrow * ROWB;
        #pragma unroll
        for (int v = 0; v < 4; v++) {
            int colb = lcol + 4 * v;
            // A: hi, lo
            uint32_t ah0 = f2bf2(ra[v].x, ra[v].y);
            uint32_t ah1 = f2bf2(ra[v].z, ra[v].w);
            float2 hf0 = __bfloat1622float2(*reinterpret_cast<__nv_bfloat162*>(&ah0));
            float2 hf1 = __bfloat1622float2(*reinterpret_cast<__nv_bfloat162*>(&ah1));
            uint32_t al0 = f2bf2(ra[v].x - hf0.x, ra[v].y - hf0.y);
            uint32_t al1 = f2bf2(ra[v].z - hf1.x, ra[v].w - hf1.y);
            *reinterpret_cast<uint2*>(base + rowoff + (uint32_t)(colb) * 2)      = make_uint2(ah0, ah1);
            *reinterpret_cast<uint2*>(base + rowoff + (uint32_t)(64 + colb) * 2) = make_uint2(ah0, ah1);
            *reinterpret_cast<uint2*>(base + rowoff + (uint32_t)(32 + colb) * 2) = make_uint2(al0, al1);
            // B: hi, hi, lo
            uint32_t bh0 = f2bf2(rb[v].x, rb[v].y);
            uint32_t bh1 = f2bf2(rb[v].z, rb[v].w);
            float2 gf0 = __bfloat1622float2(*reinterpret_cast<__nv_bfloat162*>(&bh0));
            float2 gf1 = __bfloat1622float2(*reinterpret_cast<__nv_bfloat162*>(&bh1));
            uint32_t bl0 = f2bf2(rb[v].x - gf0.x, rb[v].y - gf0.y);
            uint32_t bl1 = f2bf2(rb[v].z - gf1.x, rb[v].w - gf1.y);
            char* bbase = base + ASZ;
            *reinterpret_cast<uint2*>(bbase + rowoff + (uint32_t)(colb) * 2)      = make_uint2(bh0, bh1);
            *reinterpret_cast<uint2*>(bbase + rowoff + (uint32_t)(32 + colb) * 2) = make_uint2(bh0, bh1);
            *reinterpret_cast<uint2*>(bbase + rowoff + (uint32_t)(64 + colb) * 2) = make_uint2(bl0, bl1);
        }
    }
    __syncthreads();

    const int nk = K / 32;
    for (int j = 0; j < nk; j++) {
        // prefetch next chunk into registers (overlaps MMA below)
        if (j + 1 < nk) {
            int k0 = (j + 1) * 32;
            #pragma unroll
            for (int v = 0; v < 4; v++) {
                ra[v] = *reinterpret_cast<const float4*>(Arow + k0 + lcol + 4 * v);
                rb[v] = *reinterpret_cast<const float4*>(Brow + k0 + lcol + 4 * v);
            }
        }

        // MMA over current stage: 6 k16-steps (96 bf16)
        const uint32_t stoff = (uint32_t)(j & 1) * STG;
        #pragma unroll
        for (int kk = 0; kk < 6; kk++) {
            uint32_t afr[4][4];
            uint32_t bfr[2][4];
            #pragma unroll
            for (int mt = 0; mt < 4; mt++)
                ldsm_x4(afr[mt][0], afr[mt][1], afr[mt][2], afr[mt][3],
                        aAddr + stoff + (uint32_t)mt * (16 * ROWB) + (uint32_t)kk * 32);
            #pragma unroll
            for (int nt2 = 0; nt2 < 2; nt2++)
                ldsm_x4(bfr[nt2][0], bfr[nt2][1], bfr[nt2][2], bfr[nt2][3],
                        bAddr + stoff + (uint32_t)nt2 * (16 * ROWB) + (uint32_t)kk * 32);
            #pragma unroll
            for (int mt = 0; mt < 4; mt++)
                #pragma unroll
                for (int nt = 0; nt < 4; nt++)
                    mma_bf16(acc[mt][nt], afr[mt],
                             bfr[nt >> 1][(nt & 1) * 2], bfr[nt >> 1][(nt & 1) * 2 + 1]);
        }

        // convert+store the prefetched chunk into the other stage
        if (j + 1 < nk) {
            char* base = smem + ((j + 1) & 1) * STG;
            const uint32_t rowoff = (uint32_t)lrow * ROWB;
            #pragma unroll
            for (int v = 0; v < 4; v++) {
                int colb = lcol + 4 * v;
                uint32_t ah0 = f2bf2(ra[v].x, ra[v].y);
                uint32_t ah1 = f2bf2(ra[v].z, ra[v].w);
                float2 hf0 = __bfloat1622float2(*reinterpret_cast<__nv_bfloat162*>(&ah0));
                float2 hf1 = __bfloat1622float2(*reinterpret_cast<__nv_bfloat162*>(&ah1));
                uint32_t al0 = f2bf2(ra[v].x - hf0.x, ra[v].y - hf0.y);
                uint32_t al1 = f2bf2(ra[v].z - hf1.x, ra[v].w - hf1.y);
                *reinterpret_cast<uint2*>(base + rowoff + (uint32_t)(colb) * 2)      = make_uint2(ah0, ah1);
                *reinterpret_cast<uint2*>(base + rowoff + (uint32_t)(64 + colb) * 2) = make_uint2(ah0, ah1);
                *reinterpret_cast<uint2*>(base + rowoff + (uint32_t)(32 + colb) * 2) = make_uint2(al0, al1);
                uint32_t bh0 = f2bf2(rb[v].x, rb[v].y);
                uint32_t bh1 = f2bf2(rb[v].z, rb[v].w);
                float2 gf0 = __bfloat1622float2(*reinterpret_cast<__nv_bfloat162*>(&bh0));
                float2 gf1 = __bfloat1622float2(*reinterpret_cast<__nv_bfloat162*>(&bh1));
                uint32_t bl0 = f2bf2(rb[v].x - gf0.x, rb[v].y - gf0.y);
                uint32_t bl1 = f2bf2(rb[v].z - gf1.x, rb[v].w - gf1.y);
                char* bbase = base + ASZ;
                *reinterpret_cast<uint2*>(bbase + rowoff + (uint32_t)(colb) * 2)      = make_uint2(bh0, bh1);
                *reinterpret_cast<uint2*>(bbase + rowoff + (uint32_t)(32 + colb) * 2) = make_uint2(bh0, bh1);
                *reinterpret_cast<uint2*>(bbase + rowoff + (uint32_t)(64 + colb) * 2) = make_uint2(bl0, bl1);
            }
        }
        __syncthreads();
    }

    // ---- epilogue: direct global stores ----
    const int gr = lane >> 2;
    const int gc = (lane & 3) * 2;
    #pragma unroll
    for (int mt = 0; mt < 4; mt++) {
        int r0 = bm + wm * 64 + mt * 16 + gr;
        #pragma unroll
        for (int nt = 0; nt < 4; nt++) {
            int c = bn + wn * 32 + nt * 8 + gc;
            *reinterpret_cast<float2*>(C + (long long)r0 * ldc + c) =
                make_float2(acc[mt][nt][0], acc[mt][nt][1]);
            *reinterpret_cast<float2*>(C + (long long)(r0 + 8) * ldc + c) =
                make_float2(acc[mt][nt][2], acc[mt][nt][3]);
        }
    }
}

// ---------------- RMSNorm ----------------
__global__ void __launch_bounds__(256) rmsnorm_kernel(
    const float* __restrict__ x, const float* __restrict__ w, float* __restrict__ y)
{
    int s = blockIdx.x;
    const float* rowp = x + (long long)s * HID;
    float* out = y + (long long)s * HID;
    int tid = threadIdx.x;

    float ss = 0.f;
    for (int i = tid; i < HID; i += 256) { float v = rowp[i]; ss += v * v; }
    __shared__ float red[256];
    red[tid] = ss; __syncthreads();
    for (int st = 128; st > 0; st >>= 1) { if (tid < st) red[tid] += red[tid + st]; __syncthreads(); }
    float inv = rsqrtf(red[0] / (float)HID + 1e-6f);
    for (int i = tid; i < HID; i += 256) out[i] = rowp[i] * inv * w[i];
}

// ---------------- qkv split + RoPE + V transpose ----------------
__global__ void __launch_bounds__(256) rope_split_kernel(
    const float* __restrict__ qkv,
    const float* __restrict__ cosT, const float* __restrict__ sinT,
    const int* __restrict__ pos_ids,
    float* __restrict__ q, float* __restrict__ k, float* __restrict__ vT)
{
    int s = blockIdx.x;
    int pos = pos_ids[s];
    if (pos < 0) pos = 0;
    if (pos >= SEQ) pos = SEQ - 1;
    const float* c = cosT + (long long)pos * HD;
    const float* sn = sinT + (long long)pos * HD;
    const float* rowp = qkv + (long long)s * (3 * HID);

    for (int idx = threadIdx.x; idx < HID; idx += 256) {
        int h = idx >> 7;
        int d = idx & 127;
        float qv = rowp[idx];
        float kv = rowp[HID + idx];
        float vv = rowp[2 * HID + idx];
        float qo = (d < 64) ? -rowp[idx + 64] : rowp[idx - 64];
        float ko = (d < 64) ? -rowp[HID + idx + 64] : rowp[HID + idx - 64];
        float cd = c[d], sd = sn[d];
        long long qi = ((long long)h * SEQ + s) * HD + d;
        q[qi] = qv * cd + qo * sd;
        k[qi] = kv * cd + ko * sd;
        vT[((long long)h * HD + d) * SEQ + s] = vv;
    }
}

// ---------------- causal softmax ----------------
__global__ void __launch_bounds__(256) softmax_causal_kernel(float* __restrict__ scores)
{
    int qrow = blockIdx.x;
    int head = blockIdx.y;
    float* rowp = scores + ((long long)head * SEQ + qrow) * SEQ;
    int n = qrow + 1;
    int tid = threadIdx.x;
    const float scale = 0.088388347648318447f;

    __shared__ float red[256];

    float m = -3.4e38f;
    for (int i = tid; i < n; i += 256) m = fmaxf(m, rowp[i] * scale);
    red[tid] = m; __syncthreads();
    for (int st = 128; st > 0; st >>= 1) { if (tid < st) red[tid] = fmaxf(red[tid], red[tid + st]); __syncthreads(); }
    m = red[0]; __syncthreads();

    float sum = 0.f;
    for (int i = tid; i < n; i += 256) {
        float e = expf(rowp[i] * scale - m);
        rowp[i] = e;
        sum += e;
    }
    red[tid] = sum; __syncthreads();
    for (int st = 128; st > 0; st >>= 1) { if (tid < st) red[tid] += red[tid + st]; __syncthreads(); }
    float inv = 1.f / red[0];

    for (int i = tid; i < n; i += 256) rowp[i] *= inv;
    for (int i = n + tid; i < SEQ; i += 256) rowp[i] = 0.f;
}

// ---------------- elementwise ----------------
__global__ void __launch_bounds__(256) add_kernel(float* __restrict__ a, const float* __restrict__ b, int n)
{
    int i = blockIdx.x * 256 + threadIdx.x;
    if (i < n) a[i] += b[i];
}

__global__ void __launch_bounds__(256) silu_mul_kernel(float* __restrict__ g, const float* __restrict__ u, int n)
{
    int i = blockIdx.x * 256 + threadIdx.x;
    if (i < n) {
        float x = g[i];
        g[i] = x / (1.f + expf(-x)) * u[i];
    }
}

// ---------------- orchestration ----------------
static inline void launch_gemm(const float* A, const float* B, float* C,
                               int M, int N, int K, int lda, int ldb, int ldc,
                               long long sA, long long sB, long long sC, int batch)
{
    dim3 grid(N / 128, M / 128, batch);
    gemm_nt_tc<<<grid, 256, SM_TOTAL>>>(A, B, C, K, lda, ldb, ldc, sA, sB, sC);
}

extern "C" void kernel_launch(void* const* d_in, const int* in_sizes, int n_in,
                              void* d_out, int out_size)
{
    const float* x      = (const float*)d_in[0];
    const int*   pos    = (const int*)d_in[1];
    const float* qkv_w  = (const float*)d_in[2];
    const float* o_w    = (const float*)d_in[3];
    const float* gate_w = (const float*)d_in[4];
    const float* up_w   = (const float*)d_in[5];
    const float* down_w = (const float*)d_in[6];
    const float* ln1_w  = (const float*)d_in[7];
    const float* ln2_w  = (const float*)d_in[8];
    const float* cosT   = (const float*)d_in[9];
    const float* sinT   = (const float*)d_in[10];
    float* h = (float*)d_out;

    cudaFuncSetAttribute(gemm_nt_tc, cudaFuncAttributeMaxDynamicSharedMemorySize, SM_TOTAL);

    float *y, *o, *qkv, *q, *k, *vT, *sc, *gate, *up;
    cudaGetSymbolAddress((void**)&y, g_y);
    cudaGetSymbolAddress((void**)&o, g_o);
    cudaGetSymbolAddress((void**)&qkv, g_qkv);
    cudaGetSymbolAddress((void**)&q, g_q);
    cudaGetSymbolAddress((void**)&k, g_k);
    cudaGetSymbolAddress((void**)&vT, g_vT);
    cudaGetSymbolAddress((void**)&sc, g_sc);
    cudaGetSymbolAddress((void**)&gate, g_gate);
    cudaGetSymbolAddress((void**)&up, g_up);

    cudaMemcpyAsync(h, x, sizeof(float) * SEQ * HID, cudaMemcpyDeviceToDevice, 0);

    const int nEl = SEQ * HID;
    const int nElI = SEQ * INTER;

    for (int L = 0; L < NL; L++) {
        const float* qw = qkv_w  + (size_t)L * 3 * HID * HID;
        const float* ow = o_w    + (size_t)L * HID * HID;
        const float* gw = gate_w + (size_t)L * INTER * HID;
        const float* uw = up_w   + (size_t)L * INTER * HID;
        const float* dw = down_w + (size_t)L * HID * INTER;

        // ---- attention block ----
        rmsnorm_kernel<<<SEQ, 256>>>(h, ln1_w + (size_t)L * HID, y);

        launch_gemm(y, qw, qkv, SEQ, 3 * HID, HID, HID, HID, 3 * HID, 0, 0, 0, 1);

        rope_split_kernel<<<SEQ, 256>>>(qkv, cosT, sinT, pos, q, k, vT);

        // scores = q @ k^T per head
        launch_gemm(q, k, sc, SEQ, SEQ, HD, HD, HD, SEQ,
                    (long long)SEQ * HD, (long long)SEQ * HD, (long long)SEQ * SEQ, NH);

        softmax_causal_kernel<<<dim3(SEQ, NH), 256>>>(sc);

        // attn_out = probs @ vT^T per head, strided into [S, HID]
        launch_gemm(sc, vT, y, SEQ, HD, SEQ, SEQ, SEQ, HID,
                    (long long)SEQ * SEQ, (long long)HD * SEQ, (long long)HD, NH);

        launch_gemm(y, ow, o, SEQ, HID, HID, HID, HID, HID, 0, 0, 0, 1);

        add_kernel<<<nEl / 256, 256>>>(h, o, nEl);

        // ---- MLP block ----
        rmsnorm_kernel<<<SEQ, 256>>>(h, ln2_w + (size_t)L * HID, y);

        launch_gemm(y, gw, gate, SEQ, INTER, HID, HID, HID, INTER, 0, 0, 0, 1);
        launch_gemm(y, uw, up,   SEQ, INTER, HID, HID, HID, INTER, 0, 0, 0, 1);

        silu_mul_kernel<<<nElI / 256, 256>>>(gate, up, nElI);

        launch_gemm(gate, dw, o, SEQ, HID, INTER, INTER, INTER, HID, 0, 0, 0, 1);

        add_kernel<<<nEl / 256, 256>>>(h, o, nEl);
    }
}

// round 5
// speedup vs baseline: 2.4926x; 1.1493x over previous
#include <cuda_runtime.h>
#include <cuda_bf16.h>
#include <math.h>
#include <stdint.h>

#define SEQ   1024
#define HID   4096
#define NH    32
#define HD    128
#define INTER 11008
#define NL    2

typedef __nv_bfloat16 bf16;

// ---------------- scratch (device globals; no allocations allowed) ----------
__device__ float g_y[SEQ * HID];
__device__ float g_o[SEQ * HID];
__device__ float g_qkv[SEQ * 3 * HID];
__device__ float g_sc[(size_t)NH * SEQ * SEQ];
__device__ float g_gate[SEQ * INTER];
__device__ float g_up[SEQ * INTER];

#define WMAX (3 * HID * HID)   // largest weight slice (qkv): 50.33M elems
__device__ bf16 g_bhi[WMAX], g_blo[WMAX];
__device__ bf16 g_yhi[SEQ * HID],  g_ylo[SEQ * HID];
__device__ bf16 g_qhi[SEQ * HID],  g_qlo[SEQ * HID];
__device__ bf16 g_khi[SEQ * HID],  g_klo[SEQ * HID];
__device__ bf16 g_vthi[SEQ * HID], g_vtlo[SEQ * HID];
__device__ bf16 g_phi[(size_t)NH * SEQ * SEQ], g_plo[(size_t)NH * SEQ * SEQ];
__device__ bf16 g_ghi[SEQ * INTER], g_glo[SEQ * INTER];

// ======================= helpers ==============================
__device__ __forceinline__ uint32_t smem_u32(const void* p) {
    uint32_t a;
    asm("{ .reg .u64 t; cvta.to.shared.u64 t, %1; cvt.u32.u64 %0, t; }" : "=r"(a) : "l"(p));
    return a;
}

__device__ __forceinline__ void ldsm_x4(uint32_t* r, uint32_t addr) {
    asm volatile("ldmatrix.sync.aligned.m8n8.x4.shared.b16 {%0,%1,%2,%3}, [%4];"
                 : "=r"(r[0]), "=r"(r[1]), "=r"(r[2]), "=r"(r[3]) : "r"(addr));
}

__device__ __forceinline__ void mma_bf16(float* c, const uint32_t* a, uint32_t b0, uint32_t b1) {
    asm volatile(
        "mma.sync.aligned.m16n8k16.row.col.f32.bf16.bf16.f32 "
        "{%0,%1,%2,%3}, {%4,%5,%6,%7}, {%8,%9}, {%0,%1,%2,%3};"
        : "+f"(c[0]), "+f"(c[1]), "+f"(c[2]), "+f"(c[3])
        : "r"(a[0]), "r"(a[1]), "r"(a[2]), "r"(a[3]), "r"(b0), "r"(b1));
}

#define CP16(dst, src) asm volatile("cp.async.cg.shared.global [%0], [%1], 16;" :: "r"(dst), "l"(src))
#define CP_COMMIT()    asm volatile("cp.async.commit_group;" ::: "memory")
#define CP_WAIT2()     asm volatile("cp.async.wait_group 2;" ::: "memory")

__device__ __forceinline__ void split2(float x, bf16& h, bf16& l) {
    h = __float2bfloat16(x);
    l = __float2bfloat16(x - __bfloat162float(h));
}

// ======================= pure-bf16 split-3 tensor GEMM ======================
// C[m,n] = sum_k A[m,k]*B[n,k], A = Ahi+Alo, B = Bhi+Blo (bf16 pairs).
// Computes hi*hi + lo*hi + hi*lo with fp32 accum.
// Requires M%128==0, N%128==0, K%32==0, lda/ldb %8==0.
#define ROWB   80                    // 64B data + 16B pad (conflict-free ldsm)
#define TILEB  (128 * ROWB)          // 10240 B
#define STAGEB (4 * TILEB)           // 40960 B (Ahi, Alo, Bhi, Blo)
#define STAGES 4
#define SMEM_SZ (STAGES * STAGEB)    // 163840 B

__device__ __forceinline__ void stage_load(
    uint32_t sdst,
    const bf16* __restrict__ Ahi, const bf16* __restrict__ Alo,
    const bf16* __restrict__ Bhi, const bf16* __restrict__ Blo,
    int lda, int ldb, int k0, int bm, int bn, int r0, int ge)
{
    // r0 in 0..63, second op at r0+64; ge = element offset (0,8,16,24)
    uint32_t so = sdst + (uint32_t)r0 * ROWB + (uint32_t)ge * 2;
    long long arow0 = (long long)(bm + r0) * lda + k0 + ge;
    long long arow1 = arow0 + (long long)64 * lda;
    long long brow0 = (long long)(bn + r0) * ldb + k0 + ge;
    long long brow1 = brow0 + (long long)64 * ldb;
    CP16(so,                         Ahi + arow0);
    CP16(so + 64 * ROWB,             Ahi + arow1);
    CP16(so + TILEB,                 Alo + arow0);
    CP16(so + TILEB + 64 * ROWB,     Alo + arow1);
    CP16(so + 2 * TILEB,             Bhi + brow0);
    CP16(so + 2 * TILEB + 64 * ROWB, Bhi + brow1);
    CP16(so + 3 * TILEB,             Blo + brow0);
    CP16(so + 3 * TILEB + 64 * ROWB, Blo + brow1);
}

__global__ void __launch_bounds__(256, 1)
gemm_bf16_split(const bf16* __restrict__ Ahi, const bf16* __restrict__ Alo,
                const bf16* __restrict__ Bhi, const bf16* __restrict__ Blo,
                float* __restrict__ C, int K, int lda, int ldb, int ldc,
                long long sA, long long sB, long long sC)
{
    extern __shared__ char smem[];
    const int tid = threadIdx.x;
    const int lane = tid & 31;
    const int wid = tid >> 5;
    const int wm = wid >> 2;          // 0..1  (64-row half)
    const int wn = wid & 3;           // 0..3  (32-col quarter)

    Ahi += (long long)blockIdx.z * sA;
    Alo += (long long)blockIdx.z * sA;
    Bhi += (long long)blockIdx.z * sB;
    Blo += (long long)blockIdx.z * sB;
    C   += (long long)blockIdx.z * sC;
    const int bm = blockIdx.y * 128;
    const int bn = blockIdx.x * 128;

    const uint32_t sb = smem_u32(smem);

    // loader mapping: thread -> (row r0 in 0..63, element seg ge)
    const int r0 = tid >> 2;          // 0..63
    const int ge = (tid & 3) * 8;     // 0,8,16,24 (bf16 elements; 16B each)

    // ldmatrix fragment bases (relative to stage base)
    const uint32_t aOff = (uint32_t)(wm * 64 + (lane & 15)) * ROWB + (uint32_t)(lane >> 4) * 16;
    const uint32_t bOff = (uint32_t)(wn * 32 + (((lane >> 4) << 3) | (lane & 7))) * ROWB
                        + (uint32_t)((lane >> 3) & 1) * 16;

    float acc[4][4][4];
    #pragma unroll
    for (int mt = 0; mt < 4; mt++)
        #pragma unroll
        for (int nt = 0; nt < 4; nt++)
            #pragma unroll
            for (int i = 0; i < 4; i++) acc[mt][nt][i] = 0.f;

    const int nk = K / 32;

    // prologue: fill STAGES-1 stages
    #pragma unroll
    for (int j = 0; j < STAGES - 1; j++) {
        if (j < nk)
            stage_load(sb + (uint32_t)(j % STAGES) * STAGEB,
                       Ahi, Alo, Bhi, Blo, lda, ldb, j * 32, bm, bn, r0, ge);
        CP_COMMIT();
    }

    for (int j = 0; j < nk; j++) {
        CP_WAIT2();
        __syncthreads();

        int jn = j + STAGES - 1;
        if (jn < nk)
            stage_load(sb + (uint32_t)(jn % STAGES) * STAGEB,
                       Ahi, Alo, Bhi, Blo, lda, ldb, jn * 32, bm, bn, r0, ge);
        CP_COMMIT();

        const uint32_t st = sb + (uint32_t)(j % STAGES) * STAGEB;
        #pragma unroll
        for (int kk = 0; kk < 2; kk++) {
            uint32_t ah[4][4], al[4][4], bh[2][4], bl[2][4];
            #pragma unroll
            for (int mt = 0; mt < 4; mt++) {
                uint32_t base = st + aOff + (uint32_t)mt * (16 * ROWB) + (uint32_t)kk * 32;
                ldsm_x4(ah[mt], base);
                ldsm_x4(al[mt], base + TILEB);
            }
            #pragma unroll
            for (int n2 = 0; n2 < 2; n2++) {
                uint32_t base = st + bOff + 2 * TILEB + (uint32_t)n2 * (16 * ROWB) + (uint32_t)kk * 32;
                ldsm_x4(bh[n2], base);
                ldsm_x4(bl[n2], base + TILEB);
            }
            #pragma unroll
            for (int mt = 0; mt < 4; mt++)
                #pragma unroll
                for (int nt = 0; nt < 4; nt++) {
                    uint32_t b0 = bh[nt >> 1][(nt & 1) * 2];
                    uint32_t b1 = bh[nt >> 1][(nt & 1) * 2 + 1];
                    mma_bf16(acc[mt][nt], ah[mt], b0, b1);
                    mma_bf16(acc[mt][nt], al[mt], b0, b1);
                    mma_bf16(acc[mt][nt], ah[mt],
                             bl[nt >> 1][(nt & 1) * 2], bl[nt >> 1][(nt & 1) * 2 + 1]);
                }
        }
        __syncthreads();
    }

    // epilogue: direct global stores
    const int gr = lane >> 2;
    const int gc = (lane & 3) * 2;
    #pragma unroll
    for (int mt = 0; mt < 4; mt++) {
        int row0 = bm + wm * 64 + mt * 16 + gr;
        #pragma unroll
        for (int nt = 0; nt < 4; nt++) {
            int c = bn + wn * 32 + nt * 8 + gc;
            *reinterpret_cast<float2*>(C + (long long)row0 * ldc + c) =
                make_float2(acc[mt][nt][0], acc[mt][nt][1]);
            *reinterpret_cast<float2*>(C + (long long)(row0 + 8) * ldc + c) =
                make_float2(acc[mt][nt][2], acc[mt][nt][3]);
        }
    }
}

// ---------------- generic fp32 -> bf16 hi/lo split ----------------
__global__ void __launch_bounds__(256) split_kernel(
    const float* __restrict__ in, bf16* __restrict__ hi, bf16* __restrict__ lo, long long n)
{
    long long i = ((long long)blockIdx.x * 256 + threadIdx.x) * 4;
    if (i >= n) return;
    float4 v = *reinterpret_cast<const float4*>(in + i);
    bf16 h0, h1, h2, h3, l0, l1, l2, l3;
    split2(v.x, h0, l0); split2(v.y, h1, l1); split2(v.z, h2, l2); split2(v.w, h3, l3);
    __nv_bfloat162 hh0 = {h0, h1}, hh1 = {h2, h3}, ll0 = {l0, l1}, ll1 = {l2, l3};
    *reinterpret_cast<uint2*>(hi + i) = make_uint2(
        *reinterpret_cast<uint32_t*>(&hh0), *reinterpret_cast<uint32_t*>(&hh1));
    *reinterpret_cast<uint2*>(lo + i) = make_uint2(
        *reinterpret_cast<uint32_t*>(&ll0), *reinterpret_cast<uint32_t*>(&ll1));
}

// ---------------- RMSNorm with fused split ----------------
__global__ void __launch_bounds__(256) rmsnorm_split_kernel(
    const float* __restrict__ x, const float* __restrict__ w,
    bf16* __restrict__ yhi, bf16* __restrict__ ylo)
{
    int s = blockIdx.x;
    const float* rowp = x + (long long)s * HID;
    int tid = threadIdx.x;

    float ss = 0.f;
    for (int i = tid; i < HID; i += 256) { float v = rowp[i]; ss += v * v; }
    __shared__ float red[256];
    red[tid] = ss; __syncthreads();
    for (int st = 128; st > 0; st >>= 1) { if (tid < st) red[tid] += red[tid + st]; __syncthreads(); }
    float inv = rsqrtf(red[0] / (float)HID + 1e-6f);

    bf16* oh = yhi + (long long)s * HID;
    bf16* ol = ylo + (long long)s * HID;
    for (int i = tid; i < HID; i += 256) {
        float v = rowp[i] * inv * w[i];
        bf16 h, l; split2(v, h, l);
        oh[i] = h; ol[i] = l;
    }
}

// ---------------- qkv split + RoPE + V transpose, fused hi/lo ----------------
__global__ void __launch_bounds__(256) rope_split_kernel(
    const float* __restrict__ qkv,
    const float* __restrict__ cosT, const float* __restrict__ sinT,
    const int* __restrict__ pos_ids,
    bf16* __restrict__ qhi, bf16* __restrict__ qlo,
    bf16* __restrict__ khi, bf16* __restrict__ klo,
    bf16* __restrict__ vthi, bf16* __restrict__ vtlo)
{
    int s = blockIdx.x;
    int pos = pos_ids[s];
    if (pos < 0) pos = 0;
    if (pos >= SEQ) pos = SEQ - 1;
    const float* c = cosT + (long long)pos * HD;
    const float* sn = sinT + (long long)pos * HD;
    const float* rowp = qkv + (long long)s * (3 * HID);

    for (int idx = threadIdx.x; idx < HID; idx += 256) {
        int h = idx >> 7;
        int d = idx & 127;
        float qv = rowp[idx];
        float kv = rowp[HID + idx];
        float vv = rowp[2 * HID + idx];
        float qo = (d < 64) ? -rowp[idx + 64] : rowp[idx - 64];
        float ko = (d < 64) ? -rowp[HID + idx + 64] : rowp[HID + idx - 64];
        float cd = c[d], sd = sn[d];
        float qr = qv * cd + qo * sd;
        float kr = kv * cd + ko * sd;
        long long qi = ((long long)h * SEQ + s) * HD + d;
        bf16 hh, ll;
        split2(qr, hh, ll); qhi[qi] = hh; qlo[qi] = ll;
        split2(kr, hh, ll); khi[qi] = hh; klo[qi] = ll;
        long long vi = ((long long)h * HD + d) * SEQ + s;
        split2(vv, hh, ll); vthi[vi] = hh; vtlo[vi] = ll;
    }
}

// ---------------- causal softmax with fused split ----------------
__global__ void __launch_bounds__(256) softmax_split_kernel(
    float* __restrict__ scores, bf16* __restrict__ phi, bf16* __restrict__ plo)
{
    int qrow = blockIdx.x;
    int head = blockIdx.y;
    long long off = ((long long)head * SEQ + qrow) * SEQ;
    float* rowp = scores + off;
    bf16* oh = phi + off;
    bf16* ol = plo + off;
    int n = qrow + 1;
    int tid = threadIdx.x;
    const float scale = 0.088388347648318447f;  // 1/sqrt(128)

    __shared__ float red[256];

    float m = -3.4e38f;
    for (int i = tid; i < n; i += 256) m = fmaxf(m, rowp[i] * scale);
    red[tid] = m; __syncthreads();
    for (int st = 128; st > 0; st >>= 1) { if (tid < st) red[tid] = fmaxf(red[tid], red[tid + st]); __syncthreads(); }
    m = red[0]; __syncthreads();

    float sum = 0.f;
    for (int i = tid; i < n; i += 256) {
        float e = expf(rowp[i] * scale - m);
        rowp[i] = e;
        sum += e;
    }
    red[tid] = sum; __syncthreads();
    for (int st = 128; st > 0; st >>= 1) { if (tid < st) red[tid] += red[tid + st]; __syncthreads(); }
    float inv = 1.f / red[0];

    for (int i = tid; i < n; i += 256) {
        float p = rowp[i] * inv;
        bf16 h, l; split2(p, h, l);
        oh[i] = h; ol[i] = l;
    }
    bf16 z = __float2bfloat16(0.f);
    for (int i = n + tid; i < SEQ; i += 256) { oh[i] = z; ol[i] = z; }
}

// ---------------- elementwise ----------------
__global__ void __launch_bounds__(256) add_kernel(float* __restrict__ a, const float* __restrict__ b, int n)
{
    int i = blockIdx.x * 256 + threadIdx.x;
    if (i < n) a[i] += b[i];
}

__global__ void __launch_bounds__(256) silu_mul_split_kernel(
    const float* __restrict__ g, const float* __restrict__ u,
    bf16* __restrict__ ghi, bf16* __restrict__ glo, int n)
{
    int i = blockIdx.x * 256 + threadIdx.x;
    if (i < n) {
        float x = g[i];
        float v = x / (1.f + expf(-x)) * u[i];
        bf16 h, l; split2(v, h, l);
        ghi[i] = h; glo[i] = l;
    }
}

// ---------------- orchestration ----------------
static inline void launch_gemm(const bf16* Ahi, const bf16* Alo,
                               const bf16* Bhi, const bf16* Blo, float* C,
                               int M, int N, int K, int lda, int ldb, int ldc,
                               long long sA, long long sB, long long sC, int batch)
{
    dim3 grid(N / 128, M / 128, batch);
    gemm_bf16_split<<<grid, 256, SMEM_SZ>>>(Ahi, Alo, Bhi, Blo, C, K, lda, ldb, ldc, sA, sB, sC);
}

static inline void launch_split(const float* in, bf16* hi, bf16* lo, long long n)
{
    long long blocks = (n / 4 + 255) / 256;
    split_kernel<<<(int)blocks, 256>>>(in, hi, lo, n);
}

extern "C" void kernel_launch(void* const* d_in, const int* in_sizes, int n_in,
                              void* d_out, int out_size)
{
    const float* x      = (const float*)d_in[0];
    const int*   pos    = (const int*)d_in[1];
    const float* qkv_w  = (const float*)d_in[2];
    const float* o_w    = (const float*)d_in[3];
    const float* gate_w = (const float*)d_in[4];
    const float* up_w   = (const float*)d_in[5];
    const float* down_w = (const float*)d_in[6];
    const float* ln1_w  = (const float*)d_in[7];
    const float* ln2_w  = (const float*)d_in[8];
    const float* cosT   = (const float*)d_in[9];
    const float* sinT   = (const float*)d_in[10];
    float* h = (float*)d_out;

    cudaFuncSetAttribute(gemm_bf16_split, cudaFuncAttributeMaxDynamicSharedMemorySize, SMEM_SZ);

    float *y, *o, *qkv, *sc, *gate, *up;
    bf16 *bhi, *blo, *yhi, *ylo, *qhi, *qlo, *khi, *klo, *vthi, *vtlo, *phi, *plo, *ghi, *glo;
    cudaGetSymbolAddress((void**)&y, g_y);
    cudaGetSymbolAddress((void**)&o, g_o);
    cudaGetSymbolAddress((void**)&qkv, g_qkv);
    cudaGetSymbolAddress((void**)&sc, g_sc);
    cudaGetSymbolAddress((void**)&gate, g_gate);
    cudaGetSymbolAddress((void**)&up, g_up);
    cudaGetSymbolAddress((void**)&bhi, g_bhi);
    cudaGetSymbolAddress((void**)&blo, g_blo);
    cudaGetSymbolAddress((void**)&yhi, g_yhi);
    cudaGetSymbolAddress((void**)&ylo, g_ylo);
    cudaGetSymbolAddress((void**)&qhi, g_qhi);
    cudaGetSymbolAddress((void**)&qlo, g_qlo);
    cudaGetSymbolAddress((void**)&khi, g_khi);
    cudaGetSymbolAddress((void**)&klo, g_klo);
    cudaGetSymbolAddress((void**)&vthi, g_vthi);
    cudaGetSymbolAddress((void**)&vtlo, g_vtlo);
    cudaGetSymbolAddress((void**)&phi, g_phi);
    cudaGetSymbolAddress((void**)&plo, g_plo);
    cudaGetSymbolAddress((void**)&ghi, g_ghi);
    cudaGetSymbolAddress((void**)&glo, g_glo);

    cudaMemcpyAsync(h, x, sizeof(float) * SEQ * HID, cudaMemcpyDeviceToDevice, 0);

    const int nEl = SEQ * HID;
    const int nElI = SEQ * INTER;

    for (int L = 0; L < NL; L++) {
        const float* qw = qkv_w  + (size_t)L * 3 * HID * HID;
        const float* ow = o_w    + (size_t)L * HID * HID;
        const float* gw = gate_w + (size_t)L * INTER * HID;
        const float* uw = up_w   + (size_t)L * INTER * HID;
        const float* dw = down_w + (size_t)L * HID * INTER;

        // ---- attention block ----
        rmsnorm_split_kernel<<<SEQ, 256>>>(h, ln1_w + (size_t)L * HID, yhi, ylo);

        launch_split(qw, bhi, blo, (long long)3 * HID * HID);
        launch_gemm(yhi, ylo, bhi, blo, qkv, SEQ, 3 * HID, HID, HID, HID, 3 * HID, 0, 0, 0, 1);

        rope_split_kernel<<<SEQ, 256>>>(qkv, cosT, sinT, pos, qhi, qlo, khi, klo, vthi, vtlo);

        // scores = q @ k^T per head
        launch_gemm(qhi, qlo, khi, klo, sc, SEQ, SEQ, HD, HD, HD, SEQ,
                    (long long)SEQ * HD, (long long)SEQ * HD, (long long)SEQ * SEQ, NH);

        softmax_split_kernel<<<dim3(SEQ, NH), 256>>>(sc, phi, plo);

        // attn_out = probs @ vT^T per head, strided into y[S, HID]
        launch_gemm(phi, plo, vthi, vtlo, y, SEQ, HD, SEQ, SEQ, SEQ, HID,
                    (long long)SEQ * SEQ, (long long)HD * SEQ, (long long)HD, NH);

        launch_split(y, yhi, ylo, (long long)nEl);
        launch_split(ow, bhi, blo, (long long)HID * HID);
        launch_gemm(yhi, ylo, bhi, blo, o, SEQ, HID, HID, HID, HID, HID, 0, 0, 0, 1);

        add_kernel<<<nEl / 256, 256>>>(h, o, nEl);

        // ---- MLP block ----
        rmsnorm_split_kernel<<<SEQ, 256>>>(h, ln2_w + (size_t)L * HID, yhi, ylo);

        launch_split(gw, bhi, blo, (long long)INTER * HID);
        launch_gemm(yhi, ylo, bhi, blo, gate, SEQ, INTER, HID, HID, HID, INTER, 0, 0, 0, 1);

        launch_split(uw, bhi, blo, (long long)INTER * HID);
        launch_gemm(yhi, ylo, bhi, blo, up, SEQ, INTER, HID, HID, HID, INTER, 0, 0, 0, 1);

        silu_mul_split_kernel<<<nElI / 256, 256>>>(gate, up, ghi, glo, nElI);

        launch_split(dw, bhi, blo, (long long)HID * INTER);
        launch_gemm(ghi, glo, bhi, blo, o, SEQ, HID, INTER, INTER, INTER, HID, 0, 0, 0, 1);

        add_kernel<<<nEl / 256, 256>>>(h, o, nEl);
    }
}

// round 6
// speedup vs baseline: 2.6431x; 1.0604x over previous
#include <cuda_runtime.h>
#include <cuda_bf16.h>
#include <math.h>
#include <stdint.h>

#define SEQ   1024
#define HID   4096
#define NH    32
#define HD    128
#define INTER 11008
#define NL    2

typedef __nv_bfloat16 bf16;

// ---------------- scratch (device globals; no allocations allowed) ----------
__device__ float g_y[SEQ * HID];
__device__ float g_o[SEQ * HID];
__device__ float g_qkv[SEQ * 3 * HID];
__device__ float g_sc[(size_t)NH * SEQ * SEQ];
__device__ float g_gate[SEQ * INTER];
__device__ float g_up[SEQ * INTER];

#define WMAX (3 * HID * HID)
__device__ bf16 g_bhi[WMAX], g_blo[WMAX];
__device__ bf16 g_yhi[SEQ * HID],  g_ylo[SEQ * HID];
__device__ bf16 g_qhi[SEQ * HID],  g_qlo[SEQ * HID];
__device__ bf16 g_khi[SEQ * HID],  g_klo[SEQ * HID];
__device__ bf16 g_vthi[SEQ * HID], g_vtlo[SEQ * HID];
__device__ bf16 g_phi[(size_t)NH * SEQ * SEQ], g_plo[(size_t)NH * SEQ * SEQ];
__device__ bf16 g_ghi[SEQ * INTER], g_glo[SEQ * INTER];

// ======================= helpers ==============================
__device__ __forceinline__ uint32_t smem_u32(const void* p) {
    uint32_t a;
    asm("{ .reg .u64 t; cvta.to.shared.u64 t, %1; cvt.u32.u64 %0, t; }" : "=r"(a) : "l"(p));
    return a;
}

__device__ __forceinline__ void ldsm_x4(uint32_t* r, uint32_t addr) {
    asm volatile("ldmatrix.sync.aligned.m8n8.x4.shared.b16 {%0,%1,%2,%3}, [%4];"
                 : "=r"(r[0]), "=r"(r[1]), "=r"(r[2]), "=r"(r[3]) : "r"(addr));
}

__device__ __forceinline__ void mma_bf16(float* c, const uint32_t* a, uint32_t b0, uint32_t b1) {
    asm volatile(
        "mma.sync.aligned.m16n8k16.row.col.f32.bf16.bf16.f32 "
        "{%0,%1,%2,%3}, {%4,%5,%6,%7}, {%8,%9}, {%0,%1,%2,%3};"
        : "+f"(c[0]), "+f"(c[1]), "+f"(c[2]), "+f"(c[3])
        : "r"(a[0]), "r"(a[1]), "r"(a[2]), "r"(a[3]), "r"(b0), "r"(b1));
}

#define CP16(dst, src) asm volatile("cp.async.cg.shared.global [%0], [%1], 16;" :: "r"(dst), "l"(src))
#define CP_COMMIT()    asm volatile("cp.async.commit_group;" ::: "memory")
#define CP_WAIT1()     asm volatile("cp.async.wait_group 1;" ::: "memory")

__device__ __forceinline__ void split2(float x, bf16& h, bf16& l) {
    h = __float2bfloat16(x);
    l = __float2bfloat16(x - __bfloat162float(h));
}

// ======================= pure-bf16 split-3 tensor GEMM ======================
// C[m,n] = sum_k A[m,k]*B[n,k]; A=Ahi+Alo, B=Bhi+Blo; hi*hi + lo*hi + hi*lo.
// CTA tile 256x128, warp tile 64x64 (warps 4x2), Kc=32, 3-stage cp.async.
// Requires M%256==0, N%128==0, K%32==0, lda/ldb %8==0.
// mode: 0 = plain; 1 = causal scores (skip tiles with bn >= bm+256);
//       2 = causal PV (cap K at bm+256).
#define ROWB   80
#define ATILE  (256 * ROWB)          // 20480 B
#define BTILE  (128 * ROWB)          // 10240 B
#define STAGEB (2 * ATILE + 2 * BTILE) // 61440 B
#define STAGES 3
#define SMEM_SZ (STAGES * STAGEB)    // 184320 B

__device__ __forceinline__ void stage_load(
    uint32_t sdst,
    const bf16* __restrict__ Ahi, const bf16* __restrict__ Alo,
    const bf16* __restrict__ Bhi, const bf16* __restrict__ Blo,
    int lda, int ldb, int k0, int bm, int bn, int tid)
{
    #pragma unroll
    for (int i = 0; i < 4; i++) {
        int idx = tid + i * 256;
        int r = idx >> 2, seg = (idx & 3) * 8;
        uint32_t so = sdst + (uint32_t)r * ROWB + (uint32_t)seg * 2;
        long long g = (long long)(bm + r) * lda + k0 + seg;
        CP16(so,         Ahi + g);
        CP16(so + ATILE, Alo + g);
    }
    #pragma unroll
    for (int i = 0; i < 2; i++) {
        int idx = tid + i * 256;
        int r = idx >> 2, seg = (idx & 3) * 8;
        uint32_t so = sdst + 2 * ATILE + (uint32_t)r * ROWB + (uint32_t)seg * 2;
        long long g = (long long)(bn + r) * ldb + k0 + seg;
        CP16(so,         Bhi + g);
        CP16(so + BTILE, Blo + g);
    }
}

__global__ void __launch_bounds__(256, 1)
gemm_bf16_split(const bf16* __restrict__ Ahi, const bf16* __restrict__ Alo,
                const bf16* __restrict__ Bhi, const bf16* __restrict__ Blo,
                float* __restrict__ C, int K, int lda, int ldb, int ldc,
                long long sA, long long sB, long long sC, int mode)
{
    extern __shared__ char smem[];
    const int tid = threadIdx.x;
    const int lane = tid & 31;
    const int wid = tid >> 5;
    const int wm = wid & 3;           // 0..3 (64-row quadrant)
    const int wn = wid >> 2;          // 0..1 (64-col half)

    const int bm = blockIdx.y * 256;
    const int bn = blockIdx.x * 128;
    if (mode == 1 && bn >= bm + 256) return;   // fully-masked causal tile

    Ahi += (long long)blockIdx.z * sA;
    Alo += (long long)blockIdx.z * sA;
    Bhi += (long long)blockIdx.z * sB;
    Blo += (long long)blockIdx.z * sB;
    C   += (long long)blockIdx.z * sC;

    int kend = (mode == 2) ? min(K, bm + 256) : K;
    const int nk = kend / 32;

    const uint32_t sb = smem_u32(smem);

    const uint32_t aOff = (uint32_t)(wm * 64 + (lane & 15)) * ROWB + (uint32_t)(lane >> 4) * 16;
    const uint32_t bOff = (uint32_t)(wn * 64 + (((lane >> 4) << 3) | (lane & 7))) * ROWB
                        + (uint32_t)((lane >> 3) & 1) * 16;

    float acc[4][8][4];
    #pragma unroll
    for (int mt = 0; mt < 4; mt++)
        #pragma unroll
        for (int nt = 0; nt < 8; nt++)
            #pragma unroll
            for (int i = 0; i < 4; i++) acc[mt][nt][i] = 0.f;

    // prologue: fill 2 stages
    #pragma unroll
    for (int j = 0; j < STAGES - 1; j++) {
        if (j < nk)
            stage_load(sb + (uint32_t)(j % STAGES) * STAGEB,
                       Ahi, Alo, Bhi, Blo, lda, ldb, j * 32, bm, bn, tid);
        CP_COMMIT();
    }

    for (int j = 0; j < nk; j++) {
        CP_WAIT1();
        __syncthreads();

        int jn = j + STAGES - 1;
        if (jn < nk)
            stage_load(sb + (uint32_t)(jn % STAGES) * STAGEB,
                       Ahi, Alo, Bhi, Blo, lda, ldb, jn * 32, bm, bn, tid);
        CP_COMMIT();

        const uint32_t st = sb + (uint32_t)(j % STAGES) * STAGEB;
        #pragma unroll
        for (int kk = 0; kk < 2; kk++) {
            uint32_t bh[4][4], bl[4][4];
            #pragma unroll
            for (int n2 = 0; n2 < 4; n2++) {
                uint32_t base = st + bOff + 2 * ATILE + (uint32_t)n2 * (16 * ROWB) + (uint32_t)kk * 32;
                ldsm_x4(bh[n2], base);
                ldsm_x4(bl[n2], base + BTILE);
            }
            #pragma unroll
            for (int mt = 0; mt < 4; mt++) {
                uint32_t ah[4], al[4];
                uint32_t base = st + aOff + (uint32_t)mt * (16 * ROWB) + (uint32_t)kk * 32;
                ldsm_x4(ah, base);
                ldsm_x4(al, base + ATILE);
                #pragma unroll
                for (int nt = 0; nt < 8; nt++) {
                    uint32_t b0 = bh[nt >> 1][(nt & 1) * 2];
                    uint32_t b1 = bh[nt >> 1][(nt & 1) * 2 + 1];
                    mma_bf16(acc[mt][nt], ah, b0, b1);
                    mma_bf16(acc[mt][nt], al, b0, b1);
                    mma_bf16(acc[mt][nt], ah,
                             bl[nt >> 1][(nt & 1) * 2], bl[nt >> 1][(nt & 1) * 2 + 1]);
                }
            }
        }
        __syncthreads();
    }

    // epilogue
    const int gr = lane >> 2;
    const int gc = (lane & 3) * 2;
    #pragma unroll
    for (int mt = 0; mt < 4; mt++) {
        int row0 = bm + wm * 64 + mt * 16 + gr;
        #pragma unroll
        for (int nt = 0; nt < 8; nt++) {
            int c = bn + wn * 64 + nt * 8 + gc;
            *reinterpret_cast<float2*>(C + (long long)row0 * ldc + c) =
                make_float2(acc[mt][nt][0], acc[mt][nt][1]);
            *reinterpret_cast<float2*>(C + (long long)(row0 + 8) * ldc + c) =
                make_float2(acc[mt][nt][2], acc[mt][nt][3]);
        }
    }
}

// ---------------- generic fp32 -> bf16 hi/lo split ----------------
__global__ void __launch_bounds__(256) split_kernel(
    const float* __restrict__ in, bf16* __restrict__ hi, bf16* __restrict__ lo, long long n)
{
    long long i = ((long long)blockIdx.x * 256 + threadIdx.x) * 4;
    if (i >= n) return;
    float4 v = *reinterpret_cast<const float4*>(in + i);
    bf16 h0, h1, h2, h3, l0, l1, l2, l3;
    split2(v.x, h0, l0); split2(v.y, h1, l1); split2(v.z, h2, l2); split2(v.w, h3, l3);
    __nv_bfloat162 hh0 = {h0, h1}, hh1 = {h2, h3}, ll0 = {l0, l1}, ll1 = {l2, l3};
    *reinterpret_cast<uint2*>(hi + i) = make_uint2(
        *reinterpret_cast<uint32_t*>(&hh0), *reinterpret_cast<uint32_t*>(&hh1));
    *reinterpret_cast<uint2*>(lo + i) = make_uint2(
        *reinterpret_cast<uint32_t*>(&ll0), *reinterpret_cast<uint32_t*>(&ll1));
}

// ---------------- RMSNorm with fused split ----------------
__global__ void __launch_bounds__(256) rmsnorm_split_kernel(
    const float* __restrict__ x, const float* __restrict__ w,
    bf16* __restrict__ yhi, bf16* __restrict__ ylo)
{
    int s = blockIdx.x;
    const float* rowp = x + (long long)s * HID;
    int tid = threadIdx.x;

    float ss = 0.f;
    for (int i = tid; i < HID; i += 256) { float v = rowp[i]; ss += v * v; }
    __shared__ float red[256];
    red[tid] = ss; __syncthreads();
    for (int st = 128; st > 0; st >>= 1) { if (tid < st) red[tid] += red[tid + st]; __syncthreads(); }
    float inv = rsqrtf(red[0] / (float)HID + 1e-6f);

    bf16* oh = yhi + (long long)s * HID;
    bf16* ol = ylo + (long long)s * HID;
    for (int i = tid; i < HID; i += 256) {
        float v = rowp[i] * inv * w[i];
        bf16 h, l; split2(v, h, l);
        oh[i] = h; ol[i] = l;
    }
}

// -------- RoPE q/k + coalesced V transpose (per head, per 128-s tile) -------
__global__ void __launch_bounds__(256) rope_v_kernel(
    const float* __restrict__ qkv,
    const float* __restrict__ cosT, const float* __restrict__ sinT,
    const int* __restrict__ pos_ids,
    bf16* __restrict__ qhi, bf16* __restrict__ qlo,
    bf16* __restrict__ khi, bf16* __restrict__ klo,
    bf16* __restrict__ vthi, bf16* __restrict__ vtlo)
{
    extern __shared__ uint32_t T[];   // [128][129] packed (hi,lo)
    int head = blockIdx.x;
    int st = blockIdx.y * 128;
    int tid = threadIdx.x;

    for (int i = tid; i < 128 * 128; i += 256) {
        int sl = i >> 7, d = i & 127;
        int s = st + sl;
        int pos = pos_ids[s];
        if (pos < 0) pos = 0;
        if (pos >= SEQ) pos = SEQ - 1;
        const float* rowp = qkv + (long long)s * (3 * HID);
        int idx = head * HD + d;
        float qv = rowp[idx];
        float kv = rowp[HID + idx];
        float vv = rowp[2 * HID + idx];
        float qo = (d < 64) ? -rowp[idx + 64] : rowp[idx - 64];
        float ko = (d < 64) ? -rowp[HID + idx + 64] : rowp[HID + idx - 64];
        float cd = cosT[(long long)pos * HD + d];
        float sd = sinT[(long long)pos * HD + d];
        float qr = qv * cd + qo * sd;
        float kr = kv * cd + ko * sd;
        long long qi = ((long long)head * SEQ + s) * HD + d;
        bf16 hh, ll;
        split2(qr, hh, ll); qhi[qi] = hh; qlo[qi] = ll;
        split2(kr, hh, ll); khi[qi] = hh; klo[qi] = ll;
        split2(vv, hh, ll);
        T[sl * 129 + d] = (uint32_t)__bfloat16_as_ushort(hh)
                        | ((uint32_t)__bfloat16_as_ushort(ll) << 16);
    }
    __syncthreads();
    for (int i = tid; i < 128 * 128; i += 256) {
        int d = i >> 7, sl = i & 127;
        uint32_t p = T[sl * 129 + d];
        long long vi = ((long long)head * HD + d) * SEQ + st + sl;
        vthi[vi] = __ushort_as_bfloat16((unsigned short)(p & 0xFFFF));
        vtlo[vi] = __ushort_as_bfloat16((unsigned short)(p >> 16));
    }
}

// ---------------- causal softmax with fused split ----------------
__global__ void __launch_bounds__(256) softmax_split_kernel(
    float* __restrict__ scores, bf16* __restrict__ phi, bf16* __restrict__ plo)
{
    int qrow = blockIdx.x;
    int head = blockIdx.y;
    long long off = ((long long)head * SEQ + qrow) * SEQ;
    float* rowp = scores + off;
    bf16* oh = phi + off;
    bf16* ol = plo + off;
    int n = qrow + 1;
    int tid = threadIdx.x;
    const float scale = 0.088388347648318447f;

    __shared__ float red[256];

    float m = -3.4e38f;
    for (int i = tid; i < n; i += 256) m = fmaxf(m, rowp[i] * scale);
    red[tid] = m; __syncthreads();
    for (int st = 128; st > 0; st >>= 1) { if (tid < st) red[tid] = fmaxf(red[tid], red[tid + st]); __syncthreads(); }
    m = red[0]; __syncthreads();

    float sum = 0.f;
    for (int i = tid; i < n; i += 256) {
        float e = expf(rowp[i] * scale - m);
        rowp[i] = e;
        sum += e;
    }
    red[tid] = sum; __syncthreads();
    for (int st = 128; st > 0; st >>= 1) { if (tid < st) red[tid] += red[tid + st]; __syncthreads(); }
    float inv = 1.f / red[0];

    for (int i = tid; i < n; i += 256) {
        float p = rowp[i] * inv;
        bf16 h, l; split2(p, h, l);
        oh[i] = h; ol[i] = l;
    }
    bf16 z = __float2bfloat16(0.f);
    for (int i = n + tid; i < SEQ; i += 256) { oh[i] = z; ol[i] = z; }
}

// ---------------- elementwise ----------------
__global__ void __launch_bounds__(256) add_kernel(float* __restrict__ a, const float* __restrict__ b, int n)
{
    int i = blockIdx.x * 256 + threadIdx.x;
    if (i < n) a[i] += b[i];
}

__global__ void __launch_bounds__(256) silu_mul_split_kernel(
    const float* __restrict__ g, const float* __restrict__ u,
    bf16* __restrict__ ghi, bf16* __restrict__ glo, int n)
{
    int i = blockIdx.x * 256 + threadIdx.x;
    if (i < n) {
        float x = g[i];
        float v = x / (1.f + expf(-x)) * u[i];
        bf16 h, l; split2(v, h, l);
        ghi[i] = h; glo[i] = l;
    }
}

// ---------------- orchestration ----------------
static inline void launch_gemm(const bf16* Ahi, const bf16* Alo,
                               const bf16* Bhi, const bf16* Blo, float* C,
                               int M, int N, int K, int lda, int ldb, int ldc,
                               long long sA, long long sB, long long sC, int batch, int mode)
{
    dim3 grid(N / 128, M / 256, batch);
    gemm_bf16_split<<<grid, 256, SMEM_SZ>>>(Ahi, Alo, Bhi, Blo, C, K, lda, ldb, ldc, sA, sB, sC, mode);
}

static inline void launch_split(const float* in, bf16* hi, bf16* lo, long long n)
{
    long long blocks = (n / 4 + 255) / 256;
    split_kernel<<<(int)blocks, 256>>>(in, hi, lo, n);
}

extern "C" void kernel_launch(void* const* d_in, const int* in_sizes, int n_in,
                              void* d_out, int out_size)
{
    const float* x      = (const float*)d_in[0];
    const int*   pos    = (const int*)d_in[1];
    const float* qkv_w  = (const float*)d_in[2];
    const float* o_w    = (const float*)d_in[3];
    const float* gate_w = (const float*)d_in[4];
    const float* up_w   = (const float*)d_in[5];
    const float* down_w = (const float*)d_in[6];
    const float* ln1_w  = (const float*)d_in[7];
    const float* ln2_w  = (const float*)d_in[8];
    const float* cosT   = (const float*)d_in[9];
    const float* sinT   = (const float*)d_in[10];
    float* h = (float*)d_out;

    cudaFuncSetAttribute(gemm_bf16_split, cudaFuncAttributeMaxDynamicSharedMemorySize, SMEM_SZ);
    cudaFuncSetAttribute(rope_v_kernel, cudaFuncAttributeMaxDynamicSharedMemorySize, 128 * 129 * 4);

    float *y, *o, *qkv, *sc, *gate, *up;
    bf16 *bhi, *blo, *yhi, *ylo, *qhi, *qlo, *khi, *klo, *vthi, *vtlo, *phi, *plo, *ghi, *glo;
    cudaGetSymbolAddress((void**)&y, g_y);
    cudaGetSymbolAddress((void**)&o, g_o);
    cudaGetSymbolAddress((void**)&qkv, g_qkv);
    cudaGetSymbolAddress((void**)&sc, g_sc);
    cudaGetSymbolAddress((void**)&gate, g_gate);
    cudaGetSymbolAddress((void**)&up, g_up);
    cudaGetSymbolAddress((void**)&bhi, g_bhi);
    cudaGetSymbolAddress((void**)&blo, g_blo);
    cudaGetSymbolAddress((void**)&yhi, g_yhi);
    cudaGetSymbolAddress((void**)&ylo, g_ylo);
    cudaGetSymbolAddress((void**)&qhi, g_qhi);
    cudaGetSymbolAddress((void**)&qlo, g_qlo);
    cudaGetSymbolAddress((void**)&khi, g_khi);
    cudaGetSymbolAddress((void**)&klo, g_klo);
    cudaGetSymbolAddress((void**)&vthi, g_vthi);
    cudaGetSymbolAddress((void**)&vtlo, g_vtlo);
    cudaGetSymbolAddress((void**)&phi, g_phi);
    cudaGetSymbolAddress((void**)&plo, g_plo);
    cudaGetSymbolAddress((void**)&ghi, g_ghi);
    cudaGetSymbolAddress((void**)&glo, g_glo);

    cudaMemcpyAsync(h, x, sizeof(float) * SEQ * HID, cudaMemcpyDeviceToDevice, 0);

    const int nEl = SEQ * HID;
    const int nElI = SEQ * INTER;

    for (int L = 0; L < NL; L++) {
        const float* qw = qkv_w  + (size_t)L * 3 * HID * HID;
        const float* ow = o_w    + (size_t)L * HID * HID;
        const float* gw = gate_w + (size_t)L * INTER * HID;
        const float* uw = up_w   + (size_t)L * INTER * HID;
        const float* dw = down_w + (size_t)L * HID * INTER;

        // ---- attention block ----
        rmsnorm_split_kernel<<<SEQ, 256>>>(h, ln1_w + (size_t)L * HID, yhi, ylo);

        launch_split(qw, bhi, blo, (long long)3 * HID * HID);
        launch_gemm(yhi, ylo, bhi, blo, qkv, SEQ, 3 * HID, HID, HID, HID, 3 * HID, 0, 0, 0, 1, 0);

        rope_v_kernel<<<dim3(NH, SEQ / 128), 256, 128 * 129 * 4>>>(
            qkv, cosT, sinT, pos, qhi, qlo, khi, klo, vthi, vtlo);

        // scores = q @ k^T per head (causal tile skip)
        launch_gemm(qhi, qlo, khi, klo, sc, SEQ, SEQ, HD, HD, HD, SEQ,
                    (long long)SEQ * HD, (long long)SEQ * HD, (long long)SEQ * SEQ, NH, 1);

        softmax_split_kernel<<<dim3(SEQ, NH), 256>>>(sc, phi, plo);

        // attn_out = probs @ vT^T per head (causal K cap), strided into y[S, HID]
        launch_gemm(phi, plo, vthi, vtlo, y, SEQ, HD, SEQ, SEQ, SEQ, HID,
                    (long long)SEQ * SEQ, (long long)HD * SEQ, (long long)HD, NH, 2);

        launch_split(y, yhi, ylo, (long long)nEl);
        launch_split(ow, bhi, blo, (long long)HID * HID);
        launch_gemm(yhi, ylo, bhi, blo, o, SEQ, HID, HID, HID, HID, HID, 0, 0, 0, 1, 0);

        add_kernel<<<nEl / 256, 256>>>(h, o, nEl);

        // ---- MLP block ----
        rmsnorm_split_kernel<<<SEQ, 256>>>(h, ln2_w + (size_t)L * HID, yhi, ylo);

        launch_split(gw, bhi, blo, (long long)INTER * HID);
        launch_gemm(yhi, ylo, bhi, blo, gate, SEQ, INTER, HID, HID, HID, INTER, 0, 0, 0, 1, 0);

        launch_split(uw, bhi, blo, (long long)INTER * HID);
        launch_gemm(yhi, ylo, bhi, blo, up, SEQ, INTER, HID, HID, HID, INTER, 0, 0, 0, 1, 0);

        silu_mul_split_kernel<<<nElI / 256, 256>>>(gate, up, ghi, glo, nElI);

        launch_split(dw, bhi, blo, (long long)HID * INTER);
        launch_gemm(ghi, glo, bhi, blo, o, SEQ, HID, INTER, INTER, INTER, HID, 0, 0, 0, 1, 0);

        add_kernel<<<nEl / 256, 256>>>(h, o, nEl);
    }
}

// round 7
// speedup vs baseline: 2.8414x; 1.0750x over previous
#include <cuda_runtime.h>
#include <cuda_bf16.h>
#include <math.h>
#include <stdint.h>

#define SEQ   1024
#define HID   4096
#define NH    32
#define HD    128
#define INTER 11008
#define NL    2

typedef __nv_bfloat16 bf16;

// ---------------- scratch (device globals; no allocations allowed) ----------
__device__ float g_y[SEQ * HID];
__device__ float g_o[SEQ * HID];
__device__ float g_qkv[SEQ * 3 * HID];
__device__ float g_sc[(size_t)NH * SEQ * SEQ];
__device__ float g_f[(size_t)SEQ * 2 * INTER];     // fused gate|up output

#define WMAX ((size_t)2 * INTER * HID)             // fused gate+up weight split
__device__ bf16 g_bhi[WMAX], g_blo[WMAX];
__device__ bf16 g_yhi[SEQ * HID],  g_ylo[SEQ * HID];
__device__ bf16 g_qhi[SEQ * HID],  g_qlo[SEQ * HID];
__device__ bf16 g_khi[SEQ * HID],  g_klo[SEQ * HID];
__device__ bf16 g_vthi[SEQ * HID], g_vtlo[SEQ * HID];
__device__ bf16 g_phi[(size_t)NH * SEQ * SEQ], g_plo[(size_t)NH * SEQ * SEQ];
__device__ bf16 g_ghi[SEQ * INTER], g_glo[SEQ * INTER];

// ======================= helpers ==============================
__device__ __forceinline__ uint32_t smem_u32(const void* p) {
    uint32_t a;
    asm("{ .reg .u64 t; cvta.to.shared.u64 t, %1; cvt.u32.u64 %0, t; }" : "=r"(a) : "l"(p));
    return a;
}

__device__ __forceinline__ void ldsm_x4(uint32_t* r, uint32_t addr) {
    asm volatile("ldmatrix.sync.aligned.m8n8.x4.shared.b16 {%0,%1,%2,%3}, [%4];"
                 : "=r"(r[0]), "=r"(r[1]), "=r"(r[2]), "=r"(r[3]) : "r"(addr));
}

__device__ __forceinline__ void mma_bf16(float* c, const uint32_t* a, uint32_t b0, uint32_t b1) {
    asm volatile(
        "mma.sync.aligned.m16n8k16.row.col.f32.bf16.bf16.f32 "
        "{%0,%1,%2,%3}, {%4,%5,%6,%7}, {%8,%9}, {%0,%1,%2,%3};"
        : "+f"(c[0]), "+f"(c[1]), "+f"(c[2]), "+f"(c[3])
        : "r"(a[0]), "r"(a[1]), "r"(a[2]), "r"(a[3]), "r"(b0), "r"(b1));
}

#define CP16(dst, src) asm volatile("cp.async.cg.shared.global [%0], [%1], 16;" :: "r"(dst), "l"(src))
#define CP_COMMIT()    asm volatile("cp.async.commit_group;" ::: "memory")
#define CP_WAIT1()     asm volatile("cp.async.wait_group 1;" ::: "memory")

__device__ __forceinline__ void split2(float x, bf16& h, bf16& l) {
    h = __float2bfloat16(x);
    l = __float2bfloat16(x - __bfloat162float(h));
}

// ======================= pure-bf16 split-3 tensor GEMM ======================
// C[m,n] = sum_k A[m,k]*B[n,k]; A=Ahi+Alo, B=Bhi+Blo; hi*hi + lo*hi + hi*lo.
// CTA tile 256x128, warp tile 64x64 (warps 4x2), Kc=32, 3-stage cp.async.
// grid = (M/256, N/128, batch): consecutive CTAs share the B (weight) tile -> L2 reuse.
// mode: 0 = plain; 1 = causal scores (skip bn >= bm+256); 2 = causal PV (cap K at bm+256).
#define ROWB   80
#define ATILE  (256 * ROWB)
#define BTILE  (128 * ROWB)
#define STAGEB (2 * ATILE + 2 * BTILE)
#define STAGES 3
#define SMEM_SZ (STAGES * STAGEB)    // 184320 B

__device__ __forceinline__ void stage_load(
    uint32_t sdst,
    const bf16* __restrict__ Ahi, const bf16* __restrict__ Alo,
    const bf16* __restrict__ Bhi, const bf16* __restrict__ Blo,
    int lda, int ldb, int k0, int bm, int bn, int tid)
{
    #pragma unroll
    for (int i = 0; i < 4; i++) {
        int idx = tid + i * 256;
        int r = idx >> 2, seg = (idx & 3) * 8;
        uint32_t so = sdst + (uint32_t)r * ROWB + (uint32_t)seg * 2;
        long long g = (long long)(bm + r) * lda + k0 + seg;
        CP16(so,         Ahi + g);
        CP16(so + ATILE, Alo + g);
    }
    #pragma unroll
    for (int i = 0; i < 2; i++) {
        int idx = tid + i * 256;
        int r = idx >> 2, seg = (idx & 3) * 8;
        uint32_t so = sdst + 2 * ATILE + (uint32_t)r * ROWB + (uint32_t)seg * 2;
        long long g = (long long)(bn + r) * ldb + k0 + seg;
        CP16(so,         Bhi + g);
        CP16(so + BTILE, Blo + g);
    }
}

__global__ void __launch_bounds__(256, 1)
gemm_bf16_split(const bf16* __restrict__ Ahi, const bf16* __restrict__ Alo,
                const bf16* __restrict__ Bhi, const bf16* __restrict__ Blo,
                float* __restrict__ C, int K, int lda, int ldb, int ldc,
                long long sA, long long sB, long long sC, int mode)
{
    extern __shared__ char smem[];
    const int tid = threadIdx.x;
    const int lane = tid & 31;
    const int wid = tid >> 5;
    const int wm = wid & 3;
    const int wn = wid >> 2;

    const int bm = blockIdx.x * 256;
    const int bn = blockIdx.y * 128;
    if (mode == 1 && bn >= bm + 256) return;

    Ahi += (long long)blockIdx.z * sA;
    Alo += (long long)blockIdx.z * sA;
    Bhi += (long long)blockIdx.z * sB;
    Blo += (long long)blockIdx.z * sB;
    C   += (long long)blockIdx.z * sC;

    int kend = (mode == 2) ? min(K, bm + 256) : K;
    const int nk = kend / 32;

    const uint32_t sb = smem_u32(smem);

    const uint32_t aOff = (uint32_t)(wm * 64 + (lane & 15)) * ROWB + (uint32_t)(lane >> 4) * 16;
    const uint32_t bOff = (uint32_t)(wn * 64 + (((lane >> 4) << 3) | (lane & 7))) * ROWB
                        + (uint32_t)((lane >> 3) & 1) * 16;

    float acc[4][8][4];
    #pragma unroll
    for (int mt = 0; mt < 4; mt++)
        #pragma unroll
        for (int nt = 0; nt < 8; nt++)
            #pragma unroll
            for (int i = 0; i < 4; i++) acc[mt][nt][i] = 0.f;

    #pragma unroll
    for (int j = 0; j < STAGES - 1; j++) {
        if (j < nk)
            stage_load(sb + (uint32_t)(j % STAGES) * STAGEB,
                       Ahi, Alo, Bhi, Blo, lda, ldb, j * 32, bm, bn, tid);
        CP_COMMIT();
    }

    for (int j = 0; j < nk; j++) {
        CP_WAIT1();
        __syncthreads();     // stage j ready + all warps done reading stage being overwritten

        int jn = j + STAGES - 1;
        if (jn < nk)
            stage_load(sb + (uint32_t)(jn % STAGES) * STAGEB,
                       Ahi, Alo, Bhi, Blo, lda, ldb, jn * 32, bm, bn, tid);
        CP_COMMIT();

        const uint32_t st = sb + (uint32_t)(j % STAGES) * STAGEB;
        #pragma unroll
        for (int kk = 0; kk < 2; kk++) {
            uint32_t bh[4][4], bl[4][4];
            #pragma unroll
            for (int n2 = 0; n2 < 4; n2++) {
                uint32_t base = st + bOff + 2 * ATILE + (uint32_t)n2 * (16 * ROWB) + (uint32_t)kk * 32;
                ldsm_x4(bh[n2], base);
                ldsm_x4(bl[n2], base + BTILE);
            }
            #pragma unroll
            for (int mt = 0; mt < 4; mt++) {
                uint32_t ah[4], al[4];
                uint32_t base = st + aOff + (uint32_t)mt * (16 * ROWB) + (uint32_t)kk * 32;
                ldsm_x4(ah, base);
                ldsm_x4(al, base + ATILE);
                #pragma unroll
                for (int nt = 0; nt < 8; nt++) {
                    uint32_t b0 = bh[nt >> 1][(nt & 1) * 2];
                    uint32_t b1 = bh[nt >> 1][(nt & 1) * 2 + 1];
                    mma_bf16(acc[mt][nt], ah, b0, b1);
                    mma_bf16(acc[mt][nt], al, b0, b1);
                    mma_bf16(acc[mt][nt], ah,
                             bl[nt >> 1][(nt & 1) * 2], bl[nt >> 1][(nt & 1) * 2 + 1]);
                }
            }
        }
    }

    const int gr = lane >> 2;
    const int gc = (lane & 3) * 2;
    #pragma unroll
    for (int mt = 0; mt < 4; mt++) {
        int row0 = bm + wm * 64 + mt * 16 + gr;
        #pragma unroll
        for (int nt = 0; nt < 8; nt++) {
            int c = bn + wn * 64 + nt * 8 + gc;
            *reinterpret_cast<float2*>(C + (long long)row0 * ldc + c) =
                make_float2(acc[mt][nt][0], acc[mt][nt][1]);
            *reinterpret_cast<float2*>(C + (long long)(row0 + 8) * ldc + c) =
                make_float2(acc[mt][nt][2], acc[mt][nt][3]);
        }
    }
}

// ---------------- generic fp32 -> bf16 hi/lo split ----------------
__global__ void __launch_bounds__(256) split_kernel(
    const float* __restrict__ in, bf16* __restrict__ hi, bf16* __restrict__ lo, long long n)
{
    long long i = ((long long)blockIdx.x * 256 + threadIdx.x) * 4;
    if (i >= n) return;
    float4 v = *reinterpret_cast<const float4*>(in + i);
    bf16 h0, h1, h2, h3, l0, l1, l2, l3;
    split2(v.x, h0, l0); split2(v.y, h1, l1); split2(v.z, h2, l2); split2(v.w, h3, l3);
    __nv_bfloat162 hh0 = {h0, h1}, hh1 = {h2, h3}, ll0 = {l0, l1}, ll1 = {l2, l3};
    *reinterpret_cast<uint2*>(hi + i) = make_uint2(
        *reinterpret_cast<uint32_t*>(&hh0), *reinterpret_cast<uint32_t*>(&hh1));
    *reinterpret_cast<uint2*>(lo + i) = make_uint2(
        *reinterpret_cast<uint32_t*>(&ll0), *reinterpret_cast<uint32_t*>(&ll1));
}

// ---------------- RMSNorm with fused split ----------------
__global__ void __launch_bounds__(256) rmsnorm_split_kernel(
    const float* __restrict__ x, const float* __restrict__ w,
    bf16* __restrict__ yhi, bf16* __restrict__ ylo)
{
    int s = blockIdx.x;
    const float* rowp = x + (long long)s * HID;
    int tid = threadIdx.x;

    float ss = 0.f;
    for (int i = tid; i < HID; i += 256) { float v = rowp[i]; ss += v * v; }
    __shared__ float red[256];
    red[tid] = ss; __syncthreads();
    for (int st = 128; st > 0; st >>= 1) { if (tid < st) red[tid] += red[tid + st]; __syncthreads(); }
    float inv = rsqrtf(red[0] / (float)HID + 1e-6f);

    bf16* oh = yhi + (long long)s * HID;
    bf16* ol = ylo + (long long)s * HID;
    for (int i = tid; i < HID; i += 256) {
        float v = rowp[i] * inv * w[i];
        bf16 h, l; split2(v, h, l);
        oh[i] = h; ol[i] = l;
    }
}

// ------------ fused residual add + RMSNorm + split (h updated) -------------
__global__ void __launch_bounds__(256) add_rms_split_kernel(
    float* __restrict__ h, const float* __restrict__ o, const float* __restrict__ w,
    bf16* __restrict__ yhi, bf16* __restrict__ ylo)
{
    int s = blockIdx.x;
    long long base = (long long)s * HID;
    int tid = threadIdx.x;
    __shared__ float v[HID];
    __shared__ float red[256];

    float ss = 0.f;
    for (int i = tid; i < HID; i += 256) {
        float t = h[base + i] + o[base + i];
        h[base + i] = t;
        v[i] = t;
        ss += t * t;
    }
    red[tid] = ss; __syncthreads();
    for (int st = 128; st > 0; st >>= 1) { if (tid < st) red[tid] += red[tid + st]; __syncthreads(); }
    float inv = rsqrtf(red[0] / (float)HID + 1e-6f);

    bf16* oh = yhi + base;
    bf16* ol = ylo + base;
    for (int i = tid; i < HID; i += 256) {
        float t = v[i] * inv * w[i];
        bf16 hh, ll; split2(t, hh, ll);
        oh[i] = hh; ol[i] = ll;
    }
}

// -------- RoPE q/k + coalesced V transpose (per head, per 128-s tile) -------
__global__ void __launch_bounds__(256) rope_v_kernel(
    const float* __restrict__ qkv,
    const float* __restrict__ cosT, const float* __restrict__ sinT,
    const int* __restrict__ pos_ids,
    bf16* __restrict__ qhi, bf16* __restrict__ qlo,
    bf16* __restrict__ khi, bf16* __restrict__ klo,
    bf16* __restrict__ vthi, bf16* __restrict__ vtlo)
{
    extern __shared__ uint32_t T[];   // [128][129] packed (hi,lo)
    int head = blockIdx.x;
    int st = blockIdx.y * 128;
    int tid = threadIdx.x;

    for (int i = tid; i < 128 * 128; i += 256) {
        int sl = i >> 7, d = i & 127;
        int s = st + sl;
        int pos = pos_ids[s];
        if (pos < 0) pos = 0;
        if (pos >= SEQ) pos = SEQ - 1;
        const float* rowp = qkv + (long long)s * (3 * HID);
        int idx = head * HD + d;
        float qv = rowp[idx];
        float kv = rowp[HID + idx];
        float vv = rowp[2 * HID + idx];
        float qo = (d < 64) ? -rowp[idx + 64] : rowp[idx - 64];
        float ko = (d < 64) ? -rowp[HID + idx + 64] : rowp[HID + idx - 64];
        float cd = cosT[(long long)pos * HD + d];
        float sd = sinT[(long long)pos * HD + d];
        float qr = qv * cd + qo * sd;
        float kr = kv * cd + ko * sd;
        long long qi = ((long long)head * SEQ + s) * HD + d;
        bf16 hh, ll;
        split2(qr, hh, ll); qhi[qi] = hh; qlo[qi] = ll;
        split2(kr, hh, ll); khi[qi] = hh; klo[qi] = ll;
        split2(vv, hh, ll);
        T[sl * 129 + d] = (uint32_t)__bfloat16_as_ushort(hh)
                        | ((uint32_t)__bfloat16_as_ushort(ll) << 16);
    }
    __syncthreads();
    for (int i = tid; i < 128 * 128; i += 256) {
        int d = i >> 7, sl = i & 127;
        uint32_t p = T[sl * 129 + d];
        long long vi = ((long long)head * HD + d) * SEQ + st + sl;
        vthi[vi] = __ushort_as_bfloat16((unsigned short)(p & 0xFFFF));
        vtlo[vi] = __ushort_as_bfloat16((unsigned short)(p >> 16));
    }
}

// ---------------- causal softmax with fused split ----------------
__global__ void __launch_bounds__(256) softmax_split_kernel(
    float* __restrict__ scores, bf16* __restrict__ phi, bf16* __restrict__ plo)
{
    int qrow = blockIdx.x;
    int head = blockIdx.y;
    long long off = ((long long)head * SEQ + qrow) * SEQ;
    float* rowp = scores + off;
    bf16* oh = phi + off;
    bf16* ol = plo + off;
    int n = qrow + 1;
    int tid = threadIdx.x;
    const float scale = 0.088388347648318447f;

    __shared__ float red[256];

    float m = -3.4e38f;
    for (int i = tid; i < n; i += 256) m = fmaxf(m, rowp[i] * scale);
    red[tid] = m; __syncthreads();
    for (int st = 128; st > 0; st >>= 1) { if (tid < st) red[tid] = fmaxf(red[tid], red[tid + st]); __syncthreads(); }
    m = red[0]; __syncthreads();

    float sum = 0.f;
    for (int i = tid; i < n; i += 256) {
        float e = expf(rowp[i] * scale - m);
        rowp[i] = e;
        sum += e;
    }
    red[tid] = sum; __syncthreads();
    for (int st = 128; st > 0; st >>= 1) { if (tid < st) red[tid] += red[tid + st]; __syncthreads(); }
    float inv = 1.f / red[0];

    for (int i = tid; i < n; i += 256) {
        float p = rowp[i] * inv;
        bf16 h, l; split2(p, h, l);
        oh[i] = h; ol[i] = l;
    }
    bf16 z = __float2bfloat16(0.f);
    for (int i = n + tid; i < SEQ; i += 256) { oh[i] = z; ol[i] = z; }
}

// ---------------- elementwise ----------------
__global__ void __launch_bounds__(256) add_kernel(float* __restrict__ a, const float* __restrict__ b, int n)
{
    int i = blockIdx.x * 256 + threadIdx.x;
    if (i < n) a[i] += b[i];
}

// silu(f[:, :INTER]) * f[:, INTER:], split
__global__ void __launch_bounds__(256) silu_mul_split_kernel(
    const float* __restrict__ f, bf16* __restrict__ ghi, bf16* __restrict__ glo, int n)
{
    int i = blockIdx.x * 256 + threadIdx.x;
    if (i < n) {
        int s = i / INTER, c = i - s * INTER;
        long long base = (long long)s * (2 * INTER);
        float x = f[base + c];
        float v = x / (1.f + expf(-x)) * f[base + INTER + c];
        bf16 h, l; split2(v, h, l);
        ghi[i] = h; glo[i] = l;
    }
}

// ---------------- orchestration ----------------
static inline void launch_gemm(const bf16* Ahi, const bf16* Alo,
                               const bf16* Bhi, const bf16* Blo, float* C,
                               int M, int N, int K, int lda, int ldb, int ldc,
                               long long sA, long long sB, long long sC, int batch, int mode)
{
    dim3 grid(M / 256, N / 128, batch);
    gemm_bf16_split<<<grid, 256, SMEM_SZ>>>(Ahi, Alo, Bhi, Blo, C, K, lda, ldb, ldc, sA, sB, sC, mode);
}

static inline void launch_split(const float* in, bf16* hi, bf16* lo, long long n)
{
    long long blocks = (n / 4 + 255) / 256;
    split_kernel<<<(int)blocks, 256>>>(in, hi, lo, n);
}

extern "C" void kernel_launch(void* const* d_in, const int* in_sizes, int n_in,
                              void* d_out, int out_size)
{
    const float* x      = (const float*)d_in[0];
    const int*   pos    = (const int*)d_in[1];
    const float* qkv_w  = (const float*)d_in[2];
    const float* o_w    = (const float*)d_in[3];
    const float* gate_w = (const float*)d_in[4];
    const float* up_w   = (const float*)d_in[5];
    const float* down_w = (const float*)d_in[6];
    const float* ln1_w  = (const float*)d_in[7];
    const float* ln2_w  = (const float*)d_in[8];
    const float* cosT   = (const float*)d_in[9];
    const float* sinT   = (const float*)d_in[10];
    float* h = (float*)d_out;

    cudaFuncSetAttribute(gemm_bf16_split, cudaFuncAttributeMaxDynamicSharedMemorySize, SMEM_SZ);
    cudaFuncSetAttribute(rope_v_kernel, cudaFuncAttributeMaxDynamicSharedMemorySize, 128 * 129 * 4);

    float *y, *o, *qkv, *sc, *f;
    bf16 *bhi, *blo, *yhi, *ylo, *qhi, *qlo, *khi, *klo, *vthi, *vtlo, *phi, *plo, *ghi, *glo;
    cudaGetSymbolAddress((void**)&y, g_y);
    cudaGetSymbolAddress((void**)&o, g_o);
    cudaGetSymbolAddress((void**)&qkv, g_qkv);
    cudaGetSymbolAddress((void**)&sc, g_sc);
    cudaGetSymbolAddress((void**)&f, g_f);
    cudaGetSymbolAddress((void**)&bhi, g_bhi);
    cudaGetSymbolAddress((void**)&blo, g_blo);
    cudaGetSymbolAddress((void**)&yhi, g_yhi);
    cudaGetSymbolAddress((void**)&ylo, g_ylo);
    cudaGetSymbolAddress((void**)&qhi, g_qhi);
    cudaGetSymbolAddress((void**)&qlo, g_qlo);
    cudaGetSymbolAddress((void**)&khi, g_khi);
    cudaGetSymbolAddress((void**)&klo, g_klo);
    cudaGetSymbolAddress((void**)&vthi, g_vthi);
    cudaGetSymbolAddress((void**)&vtlo, g_vtlo);
    cudaGetSymbolAddress((void**)&phi, g_phi);
    cudaGetSymbolAddress((void**)&plo, g_plo);
    cudaGetSymbolAddress((void**)&ghi, g_ghi);
    cudaGetSymbolAddress((void**)&glo, g_glo);

    cudaMemcpyAsync(h, x, sizeof(float) * SEQ * HID, cudaMemcpyDeviceToDevice, 0);

    const int nEl = SEQ * HID;
    const int nElI = SEQ * INTER;

    // initial rmsnorm (h = x)
    rmsnorm_split_kernel<<<SEQ, 256>>>(h, ln1_w, yhi, ylo);

    for (int L = 0; L < NL; L++) {
        const float* qw = qkv_w  + (size_t)L * 3 * HID * HID;
        const float* ow = o_w    + (size_t)L * HID * HID;
        const float* gw = gate_w + (size_t)L * INTER * HID;
        const float* uw = up_w   + (size_t)L * INTER * HID;
        const float* dw = down_w + (size_t)L * HID * INTER;

        // ---- attention block (yhi/ylo already hold rmsnorm(ln1) of h) ----
        launch_split(qw, bhi, blo, (long long)3 * HID * HID);
        launch_gemm(yhi, ylo, bhi, blo, qkv, SEQ, 3 * HID, HID, HID, HID, 3 * HID, 0, 0, 0, 1, 0);

        rope_v_kernel<<<dim3(NH, SEQ / 128), 256, 128 * 129 * 4>>>(
            qkv, cosT, sinT, pos, qhi, qlo, khi, klo, vthi, vtlo);

        launch_gemm(qhi, qlo, khi, klo, sc, SEQ, SEQ, HD, HD, HD, SEQ,
                    (long long)SEQ * HD, (long long)SEQ * HD, (long long)SEQ * SEQ, NH, 1);

        softmax_split_kernel<<<dim3(SEQ, NH), 256>>>(sc, phi, plo);

        launch_gemm(phi, plo, vthi, vtlo, y, SEQ, HD, SEQ, SEQ, SEQ, HID,
                    (long long)SEQ * SEQ, (long long)HD * SEQ, (long long)HD, NH, 2);

        launch_split(y, yhi, ylo, (long long)nEl);
        launch_split(ow, bhi, blo, (long long)HID * HID);
        launch_gemm(yhi, ylo, bhi, blo, o, SEQ, HID, HID, HID, HID, HID, 0, 0, 0, 1, 0);

        // h += o; y = rmsnorm(h, ln2) split
        add_rms_split_kernel<<<SEQ, 256>>>(h, o, ln2_w + (size_t)L * HID, yhi, ylo);

        // ---- MLP block: fused gate|up GEMM (N = 2*INTER) ----
        launch_split(gw, bhi, blo, (long long)INTER * HID);
        launch_split(uw, bhi + (size_t)INTER * HID, blo + (size_t)INTER * HID, (long long)INTER * HID);
        launch_gemm(yhi, ylo, bhi, blo, f, SEQ, 2 * INTER, HID, HID, HID, 2 * INTER, 0, 0, 0, 1, 0);

        silu_mul_split_kernel<<<nElI / 256, 256>>>(f, ghi, glo, nElI);

        launch_split(dw, bhi, blo, (long long)HID * INTER);
        launch_gemm(ghi, glo, bhi, blo, o, SEQ, HID, INTER, INTER, INTER, HID, 0, 0, 0, 1, 0);

        if (L < NL - 1) {
            add_rms_split_kernel<<<SEQ, 256>>>(h, o, ln1_w + (size_t)(L + 1) * HID, yhi, ylo);
        } else {
            add_kernel<<<nEl / 256, 256>>>(h, o, nEl);
        }
    }
}

// round 8
// speedup vs baseline: 2.9452x; 1.0366x over previous
#include <cuda_runtime.h>
#include <cuda_bf16.h>
#include <math.h>
#include <stdint.h>

#define SEQ   1024
#define HID   4096
#define NH    32
#define HD    128
#define INTER 11008
#define NL    2

typedef __nv_bfloat16 bf16;

// ---------------- scratch (device globals; no allocations allowed) ----------
__device__ float g_y[SEQ * HID];
__device__ float g_o[SEQ * HID];
__device__ float g_qkv[SEQ * 3 * HID];
__device__ float g_sc[(size_t)NH * SEQ * SEQ];
__device__ float g_f[(size_t)SEQ * 2 * INTER];     // fused gate|up output

__device__ bf16 g_yhi[SEQ * HID],  g_ylo[SEQ * HID];
__device__ bf16 g_qhi[SEQ * HID],  g_qlo[SEQ * HID];
__device__ bf16 g_khi[SEQ * HID],  g_klo[SEQ * HID];
__device__ bf16 g_vthi[SEQ * HID], g_vtlo[SEQ * HID];
__device__ bf16 g_phi[(size_t)NH * SEQ * SEQ], g_plo[(size_t)NH * SEQ * SEQ];
__device__ bf16 g_ghi[SEQ * INTER], g_glo[SEQ * INTER];

// ======================= helpers ==============================
__device__ __forceinline__ uint32_t smem_u32(const void* p) {
    uint32_t a;
    asm("{ .reg .u64 t; cvta.to.shared.u64 t, %1; cvt.u32.u64 %0, t; }" : "=r"(a) : "l"(p));
    return a;
}

__device__ __forceinline__ void ldsm_x4(uint32_t* r, uint32_t addr) {
    asm volatile("ldmatrix.sync.aligned.m8n8.x4.shared.b16 {%0,%1,%2,%3}, [%4];"
                 : "=r"(r[0]), "=r"(r[1]), "=r"(r[2]), "=r"(r[3]) : "r"(addr));
}

__device__ __forceinline__ void mma_bf16(float* c, const uint32_t* a, uint32_t b0, uint32_t b1) {
    asm volatile(
        "mma.sync.aligned.m16n8k16.row.col.f32.bf16.bf16.f32 "
        "{%0,%1,%2,%3}, {%4,%5,%6,%7}, {%8,%9}, {%0,%1,%2,%3};"
        : "+f"(c[0]), "+f"(c[1]), "+f"(c[2]), "+f"(c[3])
        : "r"(a[0]), "r"(a[1]), "r"(a[2]), "r"(a[3]), "r"(b0), "r"(b1));
}

#define CP16(dst, src) asm volatile("cp.async.cg.shared.global [%0], [%1], 16;" :: "r"(dst), "l"(src))
#define CP_COMMIT()    asm volatile("cp.async.commit_group;" ::: "memory")
#define CP_WAIT1()     asm volatile("cp.async.wait_group 1;" ::: "memory")

__device__ __forceinline__ void split2(float x, bf16& h, bf16& l) {
    h = __float2bfloat16(x);
    l = __float2bfloat16(x - __bfloat162float(h));
}

__device__ __forceinline__ uint32_t pk(bf16 a, bf16 b) {
    return (uint32_t)__bfloat16_as_ushort(a) | ((uint32_t)__bfloat16_as_ushort(b) << 16);
}

// ==================== shared tile geometry ====================
#define ROWB   80
#define ATILE  (256 * ROWB)              // 20480 B
#define BTILE  (128 * ROWB)              // 10240 B
#define STAGEB (2 * ATILE + 2 * BTILE)   // 61440 B
#define STAGES 3
#define SMEM_SZ (STAGES * STAGEB)        // 184320 B

// A (activations, bf16 hi/lo) stage loader via cp.async
__device__ __forceinline__ void a_stage_load(
    uint32_t sdst, const bf16* __restrict__ Ahi, const bf16* __restrict__ Alo,
    int lda, int k0, int bm, int tid)
{
    #pragma unroll
    for (int i = 0; i < 4; i++) {
        int idx = tid + i * 256;
        int r = idx >> 2, seg = (idx & 3) * 8;
        uint32_t so = sdst + (uint32_t)r * ROWB + (uint32_t)seg * 2;
        long long g = (long long)(bm + r) * lda + k0 + seg;
        CP16(so,         Ahi + g);
        CP16(so + ATILE, Alo + g);
    }
}

// ============ GEMM 1: A bf16 hi/lo  ×  B fp32 weights (in-kernel split) ======
// C[m,n] = sum_k A[m,k] * W[n,k].  B rows: n<N1 -> B1, else B2 (fused gate|up).
// CTA 256x128, warp 64x64, Kc=32, A 3-stage cp.async, B reg-prefetch + convert.
__global__ void __launch_bounds__(256, 1)
gemm_wsplit(const bf16* __restrict__ Ahi, const bf16* __restrict__ Alo,
            const float* __restrict__ B1, const float* __restrict__ B2, int N1,
            float* __restrict__ C, int K, int lda, int ldb, int ldc)
{
    extern __shared__ char smem[];
    const int tid = threadIdx.x;
    const int lane = tid & 31;
    const int wid = tid >> 5;
    const int wm = wid & 3;
    const int wn = wid >> 2;

    const int bm = blockIdx.x * 256;
    const int bn = blockIdx.y * 128;

    const float* W = (bn < N1) ? (B1 + (long long)bn * ldb)
                               : (B2 + (long long)(bn - N1) * ldb);

    const uint32_t sb = smem_u32(smem);
    const int nk = K / 32;

    // B loader mapping: 2 threads per row, 16 fp32 each
    const int br = tid >> 1;
    const int bc = (tid & 1) * 16;
    const float* Wrow = W + (long long)br * ldb + bc;
    const uint32_t bsts = (uint32_t)br * ROWB + (uint32_t)bc * 2;   // offset in Bhi tile

    const uint32_t aOff = (uint32_t)(wm * 64 + (lane & 15)) * ROWB + (uint32_t)(lane >> 4) * 16;
    const uint32_t bOff = (uint32_t)(wn * 64 + (((lane >> 4) << 3) | (lane & 7))) * ROWB
                        + (uint32_t)((lane >> 3) & 1) * 16;

    float acc[4][8][4];
    #pragma unroll
    for (int mt = 0; mt < 4; mt++)
        #pragma unroll
        for (int nt = 0; nt < 8; nt++)
            #pragma unroll
            for (int i = 0; i < 4; i++) acc[mt][nt][i] = 0.f;

    float4 rB[4];

    // ---- prologue ----
    // B(0): load, convert, STS to stage 0
    #pragma unroll
    for (int v = 0; v < 4; v++) rB[v] = *reinterpret_cast<const float4*>(Wrow + v * 4);
    {
        uint32_t dhi = sb + 2 * ATILE + bsts;
        bf16 h0,h1,h2,h3,l0,l1,l2,l3;
        uint32_t hw[4], lw[4];
        #pragma unroll
        for (int v = 0; v < 4; v++) {
            split2(rB[v].x, h0, l0); split2(rB[v].y, h1, l1);
            split2(rB[v].z, h2, l2); split2(rB[v].w, h3, l3);
            hw[v] = 0; lw[v] = 0;   // placate compiler
            hw[v] = pk(h0, h1); lw[v] = pk(l0, l1);
            // store two bf16x2 per float4
            *reinterpret_cast<uint2*>(smem + (dhi - sb) + v * 8) = make_uint2(pk(h0,h1), pk(h2,h3));
            *reinterpret_cast<uint2*>(smem + (dhi - sb) + BTILE + v * 8) = make_uint2(pk(l0,l1), pk(l2,l3));
        }
    }
    // A stages 0,1 via cp.async
    a_stage_load(sb, Ahi, Alo, lda, 0, bm, tid);
    CP_COMMIT();
    if (nk > 1) a_stage_load(sb + STAGEB, Ahi, Alo, lda, 32, bm, tid);
    CP_COMMIT();
    // B(1) prefetch
    if (nk > 1) {
        #pragma unroll
        for (int v = 0; v < 4; v++) rB[v] = *reinterpret_cast<const float4*>(Wrow + 32 + v * 4);
    }

    for (int j = 0; j < nk; j++) {
        CP_WAIT1();
        __syncthreads();

        int jn = j + 2;
        if (jn < nk)
            a_stage_load(sb + (uint32_t)(jn % STAGES) * STAGEB, Ahi, Alo, lda, jn * 32, bm, tid);
        CP_COMMIT();

        const uint32_t st = sb + (uint32_t)(j % STAGES) * STAGEB;
        #pragma unroll
        for (int kk = 0; kk < 2; kk++) {
            uint32_t bh[4][4], bl[4][4];
            #pragma unroll
            for (int n2 = 0; n2 < 4; n2++) {
                uint32_t base = st + bOff + 2 * ATILE + (uint32_t)n2 * (16 * ROWB) + (uint32_t)kk * 32;
                ldsm_x4(bh[n2], base);
                ldsm_x4(bl[n2], base + BTILE);
            }
            #pragma unroll
            for (int mt = 0; mt < 4; mt++) {
                uint32_t ah[4], al[4];
                uint32_t base = st + aOff + (uint32_t)mt * (16 * ROWB) + (uint32_t)kk * 32;
                ldsm_x4(ah, base);
                ldsm_x4(al, base + ATILE);
                #pragma unroll
                for (int nt = 0; nt < 8; nt++) {
                    uint32_t b0 = bh[nt >> 1][(nt & 1) * 2];
                    uint32_t b1 = bh[nt >> 1][(nt & 1) * 2 + 1];
                    mma_bf16(acc[mt][nt], ah, b0, b1);
                    mma_bf16(acc[mt][nt], al, b0, b1);
                    mma_bf16(acc[mt][nt], ah,
                             bl[nt >> 1][(nt & 1) * 2], bl[nt >> 1][(nt & 1) * 2 + 1]);
                }
            }
        }

        // convert B(j+1) from regs into stage (j+1)%3
        if (j + 1 < nk) {
            uint32_t dst = sb + (uint32_t)((j + 1) % STAGES) * STAGEB + 2 * ATILE + bsts;
            bf16 h0,h1,h2,h3,l0,l1,l2,l3;
            #pragma unroll
            for (int v = 0; v < 4; v++) {
                split2(rB[v].x, h0, l0); split2(rB[v].y, h1, l1);
                split2(rB[v].z, h2, l2); split2(rB[v].w, h3, l3);
                *reinterpret_cast<uint2*>(smem + (dst - sb) + v * 8) = make_uint2(pk(h0,h1), pk(h2,h3));
                *reinterpret_cast<uint2*>(smem + (dst - sb) + BTILE + v * 8) = make_uint2(pk(l0,l1), pk(l2,l3));
            }
        }
        // prefetch B(j+2)
        if (j + 2 < nk) {
            const float* p = Wrow + (j + 2) * 32;
            #pragma unroll
            for (int v = 0; v < 4; v++) rB[v] = *reinterpret_cast<const float4*>(p + v * 4);
        }
    }

    const int gr = lane >> 2;
    const int gc = (lane & 3) * 2;
    #pragma unroll
    for (int mt = 0; mt < 4; mt++) {
        int row0 = bm + wm * 64 + mt * 16 + gr;
        #pragma unroll
        for (int nt = 0; nt < 8; nt++) {
            int c = bn + wn * 64 + nt * 8 + gc;
            *reinterpret_cast<float2*>(C + (long long)row0 * ldc + c) =
                make_float2(acc[mt][nt][0], acc[mt][nt][1]);
            *reinterpret_cast<float2*>(C + (long long)(row0 + 8) * ldc + c) =
                make_float2(acc[mt][nt][2], acc[mt][nt][3]);
        }
    }
}

// ============ GEMM 2: both operands bf16 hi/lo (attention) ==================
// mode: 1 = causal scores (skip bn >= bm+256); 2 = causal PV (cap K at bm+256).
__device__ __forceinline__ void stage_load_ab(
    uint32_t sdst,
    const bf16* __restrict__ Ahi, const bf16* __restrict__ Alo,
    const bf16* __restrict__ Bhi, const bf16* __restrict__ Blo,
    int lda, int ldb, int k0, int bm, int bn, int tid)
{
    #pragma unroll
    for (int i = 0; i < 4; i++) {
        int idx = tid + i * 256;
        int r = idx >> 2, seg = (idx & 3) * 8;
        uint32_t so = sdst + (uint32_t)r * ROWB + (uint32_t)seg * 2;
        long long g = (long long)(bm + r) * lda + k0 + seg;
        CP16(so,         Ahi + g);
        CP16(so + ATILE, Alo + g);
    }
    #pragma unroll
    for (int i = 0; i < 2; i++) {
        int idx = tid + i * 256;
        int r = idx >> 2, seg = (idx & 3) * 8;
        uint32_t so = sdst + 2 * ATILE + (uint32_t)r * ROWB + (uint32_t)seg * 2;
        long long g = (long long)(bn + r) * ldb + k0 + seg;
        CP16(so,         Bhi + g);
        CP16(so + BTILE, Blo + g);
    }
}

__global__ void __launch_bounds__(256, 1)
gemm_bf16_split(const bf16* __restrict__ Ahi, const bf16* __restrict__ Alo,
                const bf16* __restrict__ Bhi, const bf16* __restrict__ Blo,
                float* __restrict__ C, int K, int lda, int ldb, int ldc,
                long long sA, long long sB, long long sC, int mode)
{
    extern __shared__ char smem[];
    const int tid = threadIdx.x;
    const int lane = tid & 31;
    const int wid = tid >> 5;
    const int wm = wid & 3;
    const int wn = wid >> 2;

    const int bm = blockIdx.x * 256;
    const int bn = blockIdx.y * 128;
    if (mode == 1 && bn >= bm + 256) return;

    Ahi += (long long)blockIdx.z * sA;
    Alo += (long long)blockIdx.z * sA;
    Bhi += (long long)blockIdx.z * sB;
    Blo += (long long)blockIdx.z * sB;
    C   += (long long)blockIdx.z * sC;

    int kend = (mode == 2) ? min(K, bm + 256) : K;
    const int nk = kend / 32;

    const uint32_t sb = smem_u32(smem);

    const uint32_t aOff = (uint32_t)(wm * 64 + (lane & 15)) * ROWB + (uint32_t)(lane >> 4) * 16;
    const uint32_t bOff = (uint32_t)(wn * 64 + (((lane >> 4) << 3) | (lane & 7))) * ROWB
                        + (uint32_t)((lane >> 3) & 1) * 16;

    float acc[4][8][4];
    #pragma unroll
    for (int mt = 0; mt < 4; mt++)
        #pragma unroll
        for (int nt = 0; nt < 8; nt++)
            #pragma unroll
            for (int i = 0; i < 4; i++) acc[mt][nt][i] = 0.f;

    #pragma unroll
    for (int j = 0; j < STAGES - 1; j++) {
        if (j < nk)
            stage_load_ab(sb + (uint32_t)(j % STAGES) * STAGEB,
                          Ahi, Alo, Bhi, Blo, lda, ldb, j * 32, bm, bn, tid);
        CP_COMMIT();
    }

    for (int j = 0; j < nk; j++) {
        CP_WAIT1();
        __syncthreads();

        int jn = j + STAGES - 1;
        if (jn < nk)
            stage_load_ab(sb + (uint32_t)(jn % STAGES) * STAGEB,
                          Ahi, Alo, Bhi, Blo, lda, ldb, jn * 32, bm, bn, tid);
        CP_COMMIT();

        const uint32_t st = sb + (uint32_t)(j % STAGES) * STAGEB;
        #pragma unroll
        for (int kk = 0; kk < 2; kk++) {
            uint32_t bh[4][4], bl[4][4];
            #pragma unroll
            for (int n2 = 0; n2 < 4; n2++) {
                uint32_t base = st + bOff + 2 * ATILE + (uint32_t)n2 * (16 * ROWB) + (uint32_t)kk * 32;
                ldsm_x4(bh[n2], base);
                ldsm_x4(bl[n2], base + BTILE);
            }
            #pragma unroll
            for (int mt = 0; mt < 4; mt++) {
                uint32_t ah[4], al[4];
                uint32_t base = st + aOff + (uint32_t)mt * (16 * ROWB) + (uint32_t)kk * 32;
                ldsm_x4(ah, base);
                ldsm_x4(al, base + ATILE);
                #pragma unroll
                for (int nt = 0; nt < 8; nt++) {
                    uint32_t b0 = bh[nt >> 1][(nt & 1) * 2];
                    uint32_t b1 = bh[nt >> 1][(nt & 1) * 2 + 1];
                    mma_bf16(acc[mt][nt], ah, b0, b1);
                    mma_bf16(acc[mt][nt], al, b0, b1);
                    mma_bf16(acc[mt][nt], ah,
                             bl[nt >> 1][(nt & 1) * 2], bl[nt >> 1][(nt & 1) * 2 + 1]);
                }
            }
        }
    }

    const int gr = lane >> 2;
    const int gc = (lane & 3) * 2;
    #pragma unroll
    for (int mt = 0; mt < 4; mt++) {
        int row0 = bm + wm * 64 + mt * 16 + gr;
        #pragma unroll
        for (int nt = 0; nt < 8; nt++) {
            int c = bn + wn * 64 + nt * 8 + gc;
            *reinterpret_cast<float2*>(C + (long long)row0 * ldc + c) =
                make_float2(acc[mt][nt][0], acc[mt][nt][1]);
            *reinterpret_cast<float2*>(C + (long long)(row0 + 8) * ldc + c) =
                make_float2(acc[mt][nt][2], acc[mt][nt][3]);
        }
    }
}

// ---------------- fp32 -> bf16 hi/lo split (activations only) ----------------
__global__ void __launch_bounds__(256) split_kernel(
    const float* __restrict__ in, bf16* __restrict__ hi, bf16* __restrict__ lo, long long n)
{
    long long i = ((long long)blockIdx.x * 256 + threadIdx.x) * 4;
    if (i >= n) return;
    float4 v = *reinterpret_cast<const float4*>(in + i);
    bf16 h0, h1, h2, h3, l0, l1, l2, l3;
    split2(v.x, h0, l0); split2(v.y, h1, l1); split2(v.z, h2, l2); split2(v.w, h3, l3);
    *reinterpret_cast<uint2*>(hi + i) = make_uint2(pk(h0,h1), pk(h2,h3));
    *reinterpret_cast<uint2*>(lo + i) = make_uint2(pk(l0,l1), pk(l2,l3));
}

// ---------------- RMSNorm with fused split ----------------
__global__ void __launch_bounds__(256) rmsnorm_split_kernel(
    const float* __restrict__ x, const float* __restrict__ w,
    bf16* __restrict__ yhi, bf16* __restrict__ ylo)
{
    int s = blockIdx.x;
    const float* rowp = x + (long long)s * HID;
    int tid = threadIdx.x;

    float ss = 0.f;
    for (int i = tid; i < HID; i += 256) { float v = rowp[i]; ss += v * v; }
    __shared__ float red[256];
    red[tid] = ss; __syncthreads();
    for (int st = 128; st > 0; st >>= 1) { if (tid < st) red[tid] += red[tid + st]; __syncthreads(); }
    float inv = rsqrtf(red[0] / (float)HID + 1e-6f);

    bf16* oh = yhi + (long long)s * HID;
    bf16* ol = ylo + (long long)s * HID;
    for (int i = tid; i < HID; i += 256) {
        float v = rowp[i] * inv * w[i];
        bf16 h, l; split2(v, h, l);
        oh[i] = h; ol[i] = l;
    }
}

// ------------ fused residual add + RMSNorm + split (h updated) -------------
__global__ void __launch_bounds__(256) add_rms_split_kernel(
    float* __restrict__ h, const float* __restrict__ o, const float* __restrict__ w,
    bf16* __restrict__ yhi, bf16* __restrict__ ylo)
{
    int s = blockIdx.x;
    long long base = (long long)s * HID;
    int tid = threadIdx.x;
    __shared__ float v[HID];
    __shared__ float red[256];

    float ss = 0.f;
    for (int i = tid; i < HID; i += 256) {
        float t = h[base + i] + o[base + i];
        h[base + i] = t;
        v[i] = t;
        ss += t * t;
    }
    red[tid] = ss; __syncthreads();
    for (int st = 128; st > 0; st >>= 1) { if (tid < st) red[tid] += red[tid + st]; __syncthreads(); }
    float inv = rsqrtf(red[0] / (float)HID + 1e-6f);

    bf16* oh = yhi + base;
    bf16* ol = ylo + base;
    for (int i = tid; i < HID; i += 256) {
        float t = v[i] * inv * w[i];
        bf16 hh, ll; split2(t, hh, ll);
        oh[i] = hh; ol[i] = ll;
    }
}

// -------- RoPE q/k + coalesced V transpose (per head, per 128-s tile) -------
__global__ void __launch_bounds__(256) rope_v_kernel(
    const float* __restrict__ qkv,
    const float* __restrict__ cosT, const float* __restrict__ sinT,
    const int* __restrict__ pos_ids,
    bf16* __restrict__ qhi, bf16* __restrict__ qlo,
    bf16* __restrict__ khi, bf16* __restrict__ klo,
    bf16* __restrict__ vthi, bf16* __restrict__ vtlo)
{
    extern __shared__ uint32_t T[];   // [128][129] packed (hi,lo)
    int head = blockIdx.x;
    int st = blockIdx.y * 128;
    int tid = threadIdx.x;

    for (int i = tid; i < 128 * 128; i += 256) {
        int sl = i >> 7, d = i & 127;
        int s = st + sl;
        int pos = pos_ids[s];
        if (pos < 0) pos = 0;
        if (pos >= SEQ) pos = SEQ - 1;
        const float* rowp = qkv + (long long)s * (3 * HID);
        int idx = head * HD + d;
        float qv = rowp[idx];
        float kv = rowp[HID + idx];
        float vv = rowp[2 * HID + idx];
        float qo = (d < 64) ? -rowp[idx + 64] : rowp[idx - 64];
        float ko = (d < 64) ? -rowp[HID + idx + 64] : rowp[HID + idx - 64];
        float cd = cosT[(long long)pos * HD + d];
        float sd = sinT[(long long)pos * HD + d];
        float qr = qv * cd + qo * sd;
        float kr = kv * cd + ko * sd;
        long long qi = ((long long)head * SEQ + s) * HD + d;
        bf16 hh, ll;
        split2(qr, hh, ll); qhi[qi] = hh; qlo[qi] = ll;
        split2(kr, hh, ll); khi[qi] = hh; klo[qi] = ll;
        split2(vv, hh, ll);
        T[sl * 129 + d] = pk(hh, ll);
    }
    __syncthreads();
    for (int i = tid; i < 128 * 128; i += 256) {
        int d = i >> 7, sl = i & 127;
        uint32_t p = T[sl * 129 + d];
        long long vi = ((long long)head * HD + d) * SEQ + st + sl;
        vthi[vi] = __ushort_as_bfloat16((unsigned short)(p & 0xFFFF));
        vtlo[vi] = __ushort_as_bfloat16((unsigned short)(p >> 16));
    }
}

// ---------------- causal softmax with fused split ----------------
__global__ void __launch_bounds__(256) softmax_split_kernel(
    float* __restrict__ scores, bf16* __restrict__ phi, bf16* __restrict__ plo)
{
    int qrow = blockIdx.x;
    int head = blockIdx.y;
    long long off = ((long long)head * SEQ + qrow) * SEQ;
    float* rowp = scores + off;
    bf16* oh = phi + off;
    bf16* ol = plo + off;
    int n = qrow + 1;
    int tid = threadIdx.x;
    const float scale = 0.088388347648318447f;

    __shared__ float red[256];

    float m = -3.4e38f;
    for (int i = tid; i < n; i += 256) m = fmaxf(m, rowp[i] * scale);
    red[tid] = m; __syncthreads();
    for (int st = 128; st > 0; st >>= 1) { if (tid < st) red[tid] = fmaxf(red[tid], red[tid + st]); __syncthreads(); }
    m = red[0]; __syncthreads();

    float sum = 0.f;
    for (int i = tid; i < n; i += 256) {
        float e = expf(rowp[i] * scale - m);
        rowp[i] = e;
        sum += e;
    }
    red[tid] = sum; __syncthreads();
    for (int st = 128; st > 0; st >>= 1) { if (tid < st) red[tid] += red[tid + st]; __syncthreads(); }
    float inv = 1.f / red[0];

    for (int i = tid; i < n; i += 256) {
        float p = rowp[i] * inv;
        bf16 h, l; split2(p, h, l);
        oh[i] = h; ol[i] = l;
    }
    bf16 z = __float2bfloat16(0.f);
    for (int i = n + tid; i < SEQ; i += 256) { oh[i] = z; ol[i] = z; }
}

// ---------------- elementwise ----------------
__global__ void __launch_bounds__(256) add_kernel(float* __restrict__ a, const float* __restrict__ b, int n)
{
    int i = blockIdx.x * 256 + threadIdx.x;
    if (i < n) a[i] += b[i];
}

__global__ void __launch_bounds__(256) silu_mul_split_kernel(
    const float* __restrict__ f, bf16* __restrict__ ghi, bf16* __restrict__ glo, int n)
{
    int i = blockIdx.x * 256 + threadIdx.x;
    if (i < n) {
        int s = i / INTER, c = i - s * INTER;
        long long base = (long long)s * (2 * INTER);
        float x = f[base + c];
        float v = x / (1.f + expf(-x)) * f[base + INTER + c];
        bf16 h, l; split2(v, h, l);
        ghi[i] = h; glo[i] = l;
    }
}

// ---------------- orchestration ----------------
static inline void launch_gemm_w(const bf16* Ahi, const bf16* Alo,
                                 const float* B1, const float* B2, int N1, float* C,
                                 int M, int N, int K, int lda, int ldb, int ldc)
{
    dim3 grid(M / 256, N / 128);
    gemm_wsplit<<<grid, 256, SMEM_SZ>>>(Ahi, Alo, B1, B2, N1, C, K, lda, ldb, ldc);
}

static inline void launch_gemm_a(const bf16* Ahi, const bf16* Alo,
                                 const bf16* Bhi, const bf16* Blo, float* C,
                                 int M, int N, int K, int lda, int ldb, int ldc,
                                 long long sA, long long sB, long long sC, int batch, int mode)
{
    dim3 grid(M / 256, N / 128, batch);
    gemm_bf16_split<<<grid, 256, SMEM_SZ>>>(Ahi, Alo, Bhi, Blo, C, K, lda, ldb, ldc, sA, sB, sC, mode);
}

extern "C" void kernel_launch(void* const* d_in, const int* in_sizes, int n_in,
                              void* d_out, int out_size)
{
    const float* x      = (const float*)d_in[0];
    const int*   pos    = (const int*)d_in[1];
    const float* qkv_w  = (const float*)d_in[2];
    const float* o_w    = (const float*)d_in[3];
    const float* gate_w = (const float*)d_in[4];
    const float* up_w   = (const float*)d_in[5];
    const float* down_w = (const float*)d_in[6];
    const float* ln1_w  = (const float*)d_in[7];
    const float* ln2_w  = (const float*)d_in[8];
    const float* cosT   = (const float*)d_in[9];
    const float* sinT   = (const float*)d_in[10];
    float* h = (float*)d_out;

    cudaFuncSetAttribute(gemm_wsplit, cudaFuncAttributeMaxDynamicSharedMemorySize, SMEM_SZ);
    cudaFuncSetAttribute(gemm_bf16_split, cudaFuncAttributeMaxDynamicSharedMemorySize, SMEM_SZ);
    cudaFuncSetAttribute(rope_v_kernel, cudaFuncAttributeMaxDynamicSharedMemorySize, 128 * 129 * 4);

    float *y, *o, *qkv, *sc, *f;
    bf16 *yhi, *ylo, *qhi, *qlo, *khi, *klo, *vthi, *vtlo, *phi, *plo, *ghi, *glo;
    cudaGetSymbolAddress((void**)&y, g_y);
    cudaGetSymbolAddress((void**)&o, g_o);
    cudaGetSymbolAddress((void**)&qkv, g_qkv);
    cudaGetSymbolAddress((void**)&sc, g_sc);
    cudaGetSymbolAddress((void**)&f, g_f);
    cudaGetSymbolAddress((void**)&yhi, g_yhi);
    cudaGetSymbolAddress((void**)&ylo, g_ylo);
    cudaGetSymbolAddress((void**)&qhi, g_qhi);
    cudaGetSymbolAddress((void**)&qlo, g_qlo);
    cudaGetSymbolAddress((void**)&khi, g_khi);
    cudaGetSymbolAddress((void**)&klo, g_klo);
    cudaGetSymbolAddress((void**)&vthi, g_vthi);
    cudaGetSymbolAddress((void**)&vtlo, g_vtlo);
    cudaGetSymbolAddress((void**)&phi, g_phi);
    cudaGetSymbolAddress((void**)&plo, g_plo);
    cudaGetSymbolAddress((void**)&ghi, g_ghi);
    cudaGetSymbolAddress((void**)&glo, g_glo);

    cudaMemcpyAsync(h, x, sizeof(float) * SEQ * HID, cudaMemcpyDeviceToDevice, 0);

    const int nEl = SEQ * HID;
    const int nElI = SEQ * INTER;
    const int BIGN = 1 << 30;

    // initial rmsnorm (h = x)
    rmsnorm_split_kernel<<<SEQ, 256>>>(h, ln1_w, yhi, ylo);

    for (int L = 0; L < NL; L++) {
        const float* qw = qkv_w  + (size_t)L * 3 * HID * HID;
        const float* ow = o_w    + (size_t)L * HID * HID;
        const float* gw = gate_w + (size_t)L * INTER * HID;
        const float* uw = up_w   + (size_t)L * INTER * HID;
        const float* dw = down_w + (size_t)L * HID * INTER;

        // ---- attention ----
        launch_gemm_w(yhi, ylo, qw, qw, BIGN, qkv, SEQ, 3 * HID, HID, HID, HID, 3 * HID);

        rope_v_kernel<<<dim3(NH, SEQ / 128), 256, 128 * 129 * 4>>>(
            qkv, cosT, sinT, pos, qhi, qlo, khi, klo, vthi, vtlo);

        launch_gemm_a(qhi, qlo, khi, klo, sc, SEQ, SEQ, HD, HD, HD, SEQ,
                      (long long)SEQ * HD, (long long)SEQ * HD, (long long)SEQ * SEQ, NH, 1);

        softmax_split_kernel<<<dim3(SEQ, NH), 256>>>(sc, phi, plo);

        launch_gemm_a(phi, plo, vthi, vtlo, y, SEQ, HD, SEQ, SEQ, SEQ, HID,
                      (long long)SEQ * SEQ, (long long)HD * SEQ, (long long)HD, NH, 2);

        { long long n = nEl; split_kernel<<<(int)((n / 4 + 255) / 256), 256>>>(y, yhi, ylo, n); }

        launch_gemm_w(yhi, ylo, ow, ow, BIGN, o, SEQ, HID, HID, HID, HID, HID);

        add_rms_split_kernel<<<SEQ, 256>>>(h, o, ln2_w + (size_t)L * HID, yhi, ylo);

        // ---- MLP: fused gate|up ----
        launch_gemm_w(yhi, ylo, gw, uw, INTER, f, SEQ, 2 * INTER, HID, HID, HID, 2 * INTER);

        silu_mul_split_kernel<<<nElI / 256, 256>>>(f, ghi, glo, nElI);

        launch_gemm_w(ghi, glo, dw, dw, BIGN, o, SEQ, HID, INTER, INTER, INTER, HID);

        if (L < NL - 1) {
            add_rms_split_kernel<<<SEQ, 256>>>(h, o, ln1_w + (size_t)(L + 1) * HID, yhi, ylo);
        } else {
            add_kernel<<<nEl / 256, 256>>>(h, o, nEl);
        }
    }
}

// round 9
// speedup vs baseline: 2.9465x; 1.0004x over previous
#include <cuda_runtime.h>
#include <cuda_bf16.h>
#include <math.h>
#include <stdint.h>

#define SEQ   1024
#define HID   4096
#define NH    32
#define HD    128
#define INTER 11008
#define NL    2

typedef __nv_bfloat16 bf16;

// ---------------- scratch (device globals; no allocations allowed) ----------
__device__ float g_y[SEQ * HID];
__device__ float g_o[SEQ * HID];
__device__ float g_qkv[SEQ * 3 * HID];
__device__ float g_sc[(size_t)NH * SEQ * SEQ];
__device__ float g_f[(size_t)SEQ * 2 * INTER];     // fused gate|up output

__device__ bf16 g_yhi[SEQ * HID],  g_ylo[SEQ * HID];
__device__ bf16 g_qhi[SEQ * HID],  g_qlo[SEQ * HID];
__device__ bf16 g_khi[SEQ * HID],  g_klo[SEQ * HID];
__device__ bf16 g_vthi[SEQ * HID], g_vtlo[SEQ * HID];
__device__ bf16 g_phi[(size_t)NH * SEQ * SEQ], g_plo[(size_t)NH * SEQ * SEQ];
__device__ bf16 g_ghi[SEQ * INTER], g_glo[SEQ * INTER];

// ======================= helpers ==============================
__device__ __forceinline__ uint32_t smem_u32(const void* p) {
    uint32_t a;
    asm("{ .reg .u64 t; cvta.to.shared.u64 t, %1; cvt.u32.u64 %0, t; }" : "=r"(a) : "l"(p));
    return a;
}

__device__ __forceinline__ void ldsm_x4(uint32_t* r, uint32_t addr) {
    asm volatile("ldmatrix.sync.aligned.m8n8.x4.shared.b16 {%0,%1,%2,%3}, [%4];"
                 : "=r"(r[0]), "=r"(r[1]), "=r"(r[2]), "=r"(r[3]) : "r"(addr));
}

__device__ __forceinline__ void mma_bf16(float* c, const uint32_t* a, uint32_t b0, uint32_t b1) {
    asm volatile(
        "mma.sync.aligned.m16n8k16.row.col.f32.bf16.bf16.f32 "
        "{%0,%1,%2,%3}, {%4,%5,%6,%7}, {%8,%9}, {%0,%1,%2,%3};"
        : "+f"(c[0]), "+f"(c[1]), "+f"(c[2]), "+f"(c[3])
        : "r"(a[0]), "r"(a[1]), "r"(a[2]), "r"(a[3]), "r"(b0), "r"(b1));
}

#define CP16(dst, src) asm volatile("cp.async.cg.shared.global [%0], [%1], 16;" :: "r"(dst), "l"(src))
#define CP_COMMIT()    asm volatile("cp.async.commit_group;" ::: "memory")
#define CP_WAIT1()     asm volatile("cp.async.wait_group 1;" ::: "memory")

__device__ __forceinline__ void split2(float x, bf16& h, bf16& l) {
    h = __float2bfloat16(x);
    l = __float2bfloat16(x - __bfloat162float(h));
}

__device__ __forceinline__ uint32_t pk(bf16 a, bf16 b) {
    return (uint32_t)__bfloat16_as_ushort(a) | ((uint32_t)__bfloat16_as_ushort(b) << 16);
}

// ==================== shared tile geometry ====================
#define ROWB   80
#define ATILE  (256 * ROWB)              // 20480 B
#define BTILE  (128 * ROWB)              // 10240 B
#define STAGEB (2 * ATILE + 2 * BTILE)   // 61440 B
#define STAGES 3
#define SMEM_SZ (STAGES * STAGEB)        // 184320 B

__device__ __forceinline__ void a_stage_load(
    uint32_t sdst, const bf16* __restrict__ Ahi, const bf16* __restrict__ Alo,
    int lda, int k0, int bm, int tid)
{
    #pragma unroll
    for (int i = 0; i < 4; i++) {
        int idx = tid + i * 256;
        int r = idx >> 2, seg = (idx & 3) * 8;
        uint32_t so = sdst + (uint32_t)r * ROWB + (uint32_t)seg * 2;
        long long g = (long long)(bm + r) * lda + k0 + seg;
        CP16(so,         Ahi + g);
        CP16(so + ATILE, Alo + g);
    }
}

// term-major MMA block for one mt: 8x hh, 8x lh, 8x hl (acc reuse distance = 8)
#define MMA_TERM_MAJOR(accmt, ah, al, bh, bl)                                   \
    do {                                                                        \
        _Pragma("unroll")                                                       \
        for (int nt = 0; nt < 8; nt++)                                          \
            mma_bf16((accmt)[nt], ah, bh[nt >> 1][(nt & 1) * 2],                \
                     bh[nt >> 1][(nt & 1) * 2 + 1]);                            \
        _Pragma("unroll")                                                       \
        for (int nt = 0; nt < 8; nt++)                                          \
            mma_bf16((accmt)[nt], al, bh[nt >> 1][(nt & 1) * 2],                \
                     bh[nt >> 1][(nt & 1) * 2 + 1]);                            \
        _Pragma("unroll")                                                       \
        for (int nt = 0; nt < 8; nt++)                                          \
            mma_bf16((accmt)[nt], ah, bl[nt >> 1][(nt & 1) * 2],                \
                     bl[nt >> 1][(nt & 1) * 2 + 1]);                            \
    } while (0)

// ============ GEMM 1: A bf16 hi/lo  ×  B fp32 weights (in-kernel split) ======
__global__ void __launch_bounds__(256, 1)
gemm_wsplit(const bf16* __restrict__ Ahi, const bf16* __restrict__ Alo,
            const float* __restrict__ B1, const float* __restrict__ B2, int N1,
            float* __restrict__ C, int K, int lda, int ldb, int ldc)
{
    extern __shared__ char smem[];
    const int tid = threadIdx.x;
    const int lane = tid & 31;
    const int wid = tid >> 5;
    const int wm = wid & 3;
    const int wn = wid >> 2;

    const int bm = blockIdx.x * 256;
    const int bn = blockIdx.y * 128;

    const float* W = (bn < N1) ? (B1 + (long long)bn * ldb)
                               : (B2 + (long long)(bn - N1) * ldb);

    const uint32_t sb = smem_u32(smem);
    const int nk = K / 32;

    const int br = tid >> 1;
    const int bc = (tid & 1) * 16;
    const float* Wrow = W + (long long)br * ldb + bc;
    const uint32_t bsts = (uint32_t)br * ROWB + (uint32_t)bc * 2;

    const uint32_t aOff = (uint32_t)(wm * 64 + (lane & 15)) * ROWB + (uint32_t)(lane >> 4) * 16;
    const uint32_t bOff = (uint32_t)(wn * 64 + (((lane >> 4) << 3) | (lane & 7))) * ROWB
                        + (uint32_t)((lane >> 3) & 1) * 16;

    float acc[4][8][4];
    #pragma unroll
    for (int mt = 0; mt < 4; mt++)
        #pragma unroll
        for (int nt = 0; nt < 8; nt++)
            #pragma unroll
            for (int i = 0; i < 4; i++) acc[mt][nt][i] = 0.f;

    float4 rB[4];

    // ---- prologue ----
    #pragma unroll
    for (int v = 0; v < 4; v++) rB[v] = *reinterpret_cast<const float4*>(Wrow + v * 4);
    {
        bf16 h0,h1,h2,h3,l0,l1,l2,l3;
        #pragma unroll
        for (int v = 0; v < 4; v++) {
            split2(rB[v].x, h0, l0); split2(rB[v].y, h1, l1);
            split2(rB[v].z, h2, l2); split2(rB[v].w, h3, l3);
            *reinterpret_cast<uint2*>(smem + 2 * ATILE + bsts + v * 8) = make_uint2(pk(h0,h1), pk(h2,h3));
            *reinterpret_cast<uint2*>(smem + 2 * ATILE + BTILE + bsts + v * 8) = make_uint2(pk(l0,l1), pk(l2,l3));
        }
    }
    a_stage_load(sb, Ahi, Alo, lda, 0, bm, tid);
    CP_COMMIT();
    if (nk > 1) a_stage_load(sb + STAGEB, Ahi, Alo, lda, 32, bm, tid);
    CP_COMMIT();
    if (nk > 1) {
        #pragma unroll
        for (int v = 0; v < 4; v++) rB[v] = *reinterpret_cast<const float4*>(Wrow + 32 + v * 4);
    }

    for (int j = 0; j < nk; j++) {
        CP_WAIT1();
        __syncthreads();

        int jn = j + 2;
        if (jn < nk)
            a_stage_load(sb + (uint32_t)(jn % STAGES) * STAGEB, Ahi, Alo, lda, jn * 32, bm, tid);
        CP_COMMIT();

        const uint32_t st = sb + (uint32_t)(j % STAGES) * STAGEB;
        #pragma unroll
        for (int kk = 0; kk < 2; kk++) {
            uint32_t bh[4][4], bl[4][4];
            #pragma unroll
            for (int n2 = 0; n2 < 4; n2++) {
                uint32_t base = st + bOff + 2 * ATILE + (uint32_t)n2 * (16 * ROWB) + (uint32_t)kk * 32;
                ldsm_x4(bh[n2], base);
                ldsm_x4(bl[n2], base + BTILE);
            }
            #pragma unroll
            for (int mt = 0; mt < 4; mt++) {
                uint32_t ah[4], al[4];
                uint32_t base = st + aOff + (uint32_t)mt * (16 * ROWB) + (uint32_t)kk * 32;
                ldsm_x4(ah, base);
                ldsm_x4(al, base + ATILE);
                MMA_TERM_MAJOR(acc[mt], ah, al, bh, bl);
            }
        }

        if (j + 1 < nk) {
            uint32_t dst = (uint32_t)((j + 1) % STAGES) * STAGEB + 2 * ATILE + bsts;
            bf16 h0,h1,h2,h3,l0,l1,l2,l3;
            #pragma unroll
            for (int v = 0; v < 4; v++) {
                split2(rB[v].x, h0, l0); split2(rB[v].y, h1, l1);
                split2(rB[v].z, h2, l2); split2(rB[v].w, h3, l3);
                *reinterpret_cast<uint2*>(smem + dst + v * 8) = make_uint2(pk(h0,h1), pk(h2,h3));
                *reinterpret_cast<uint2*>(smem + dst + BTILE + v * 8) = make_uint2(pk(l0,l1), pk(l2,l3));
            }
        }
        if (j + 2 < nk) {
            const float* p = Wrow + (j + 2) * 32;
            #pragma unroll
            for (int v = 0; v < 4; v++) rB[v] = *reinterpret_cast<const float4*>(p + v * 4);
        }
    }

    const int gr = lane >> 2;
    const int gc = (lane & 3) * 2;
    #pragma unroll
    for (int mt = 0; mt < 4; mt++) {
        int row0 = bm + wm * 64 + mt * 16 + gr;
        #pragma unroll
        for (int nt = 0; nt < 8; nt++) {
            int c = bn + wn * 64 + nt * 8 + gc;
            *reinterpret_cast<float2*>(C + (long long)row0 * ldc + c) =
                make_float2(acc[mt][nt][0], acc[mt][nt][1]);
            *reinterpret_cast<float2*>(C + (long long)(row0 + 8) * ldc + c) =
                make_float2(acc[mt][nt][2], acc[mt][nt][3]);
        }
    }
}

// ============ GEMM 2: both operands bf16 hi/lo (attention) ==================
__device__ __forceinline__ void stage_load_ab(
    uint32_t sdst,
    const bf16* __restrict__ Ahi, const bf16* __restrict__ Alo,
    const bf16* __restrict__ Bhi, const bf16* __restrict__ Blo,
    int lda, int ldb, int k0, int bm, int bn, int tid)
{
    #pragma unroll
    for (int i = 0; i < 4; i++) {
        int idx = tid + i * 256;
        int r = idx >> 2, seg = (idx & 3) * 8;
        uint32_t so = sdst + (uint32_t)r * ROWB + (uint32_t)seg * 2;
        long long g = (long long)(bm + r) * lda + k0 + seg;
        CP16(so,         Ahi + g);
        CP16(so + ATILE, Alo + g);
    }
    #pragma unroll
    for (int i = 0; i < 2; i++) {
        int idx = tid + i * 256;
        int r = idx >> 2, seg = (idx & 3) * 8;
        uint32_t so = sdst + 2 * ATILE + (uint32_t)r * ROWB + (uint32_t)seg * 2;
        long long g = (long long)(bn + r) * ldb + k0 + seg;
        CP16(so,         Bhi + g);
        CP16(so + BTILE, Blo + g);
    }
}

__global__ void __launch_bounds__(256, 1)
gemm_bf16_split(const bf16* __restrict__ Ahi, const bf16* __restrict__ Alo,
                const bf16* __restrict__ Bhi, const bf16* __restrict__ Blo,
                float* __restrict__ C, int K, int lda, int ldb, int ldc,
                long long sA, long long sB, long long sC, int mode)
{
    extern __shared__ char smem[];
    const int tid = threadIdx.x;
    const int lane = tid & 31;
    const int wid = tid >> 5;
    const int wm = wid & 3;
    const int wn = wid >> 2;

    const int bm = blockIdx.x * 256;
    const int bn = blockIdx.y * 128;
    if (mode == 1 && bn >= bm + 256) return;

    Ahi += (long long)blockIdx.z * sA;
    Alo += (long long)blockIdx.z * sA;
    Bhi += (long long)blockIdx.z * sB;
    Blo += (long long)blockIdx.z * sB;
    C   += (long long)blockIdx.z * sC;

    int kend = (mode == 2) ? min(K, bm + 256) : K;
    const int nk = kend / 32;

    const uint32_t sb = smem_u32(smem);

    const uint32_t aOff = (uint32_t)(wm * 64 + (lane & 15)) * ROWB + (uint32_t)(lane >> 4) * 16;
    const uint32_t bOff = (uint32_t)(wn * 64 + (((lane >> 4) << 3) | (lane & 7))) * ROWB
                        + (uint32_t)((lane >> 3) & 1) * 16;

    float acc[4][8][4];
    #pragma unroll
    for (int mt = 0; mt < 4; mt++)
        #pragma unroll
        for (int nt = 0; nt < 8; nt++)
            #pragma unroll
            for (int i = 0; i < 4; i++) acc[mt][nt][i] = 0.f;

    #pragma unroll
    for (int j = 0; j < STAGES - 1; j++) {
        if (j < nk)
            stage_load_ab(sb + (uint32_t)(j % STAGES) * STAGEB,
                          Ahi, Alo, Bhi, Blo, lda, ldb, j * 32, bm, bn, tid);
        CP_COMMIT();
    }

    for (int j = 0; j < nk; j++) {
        CP_WAIT1();
        __syncthreads();

        int jn = j + STAGES - 1;
        if (jn < nk)
            stage_load_ab(sb + (uint32_t)(jn % STAGES) * STAGEB,
                          Ahi, Alo, Bhi, Blo, lda, ldb, jn * 32, bm, bn, tid);
        CP_COMMIT();

        const uint32_t st = sb + (uint32_t)(j % STAGES) * STAGEB;
        #pragma unroll
        for (int kk = 0; kk < 2; kk++) {
            uint32_t bh[4][4], bl[4][4];
            #pragma unroll
            for (int n2 = 0; n2 < 4; n2++) {
                uint32_t base = st + bOff + 2 * ATILE + (uint32_t)n2 * (16 * ROWB) + (uint32_t)kk * 32;
                ldsm_x4(bh[n2], base);
                ldsm_x4(bl[n2], base + BTILE);
            }
            #pragma unroll
            for (int mt = 0; mt < 4; mt++) {
                uint32_t ah[4], al[4];
                uint32_t base = st + aOff + (uint32_t)mt * (16 * ROWB) + (uint32_t)kk * 32;
                ldsm_x4(ah, base);
                ldsm_x4(al, base + ATILE);
                MMA_TERM_MAJOR(acc[mt], ah, al, bh, bl);
            }
        }
    }

    const int gr = lane >> 2;
    const int gc = (lane & 3) * 2;
    #pragma unroll
    for (int mt = 0; mt < 4; mt++) {
        int row0 = bm + wm * 64 + mt * 16 + gr;
        #pragma unroll
        for (int nt = 0; nt < 8; nt++) {
            int c = bn + wn * 64 + nt * 8 + gc;
            *reinterpret_cast<float2*>(C + (long long)row0 * ldc + c) =
                make_float2(acc[mt][nt][0], acc[mt][nt][1]);
            *reinterpret_cast<float2*>(C + (long long)(row0 + 8) * ldc + c) =
                make_float2(acc[mt][nt][2], acc[mt][nt][3]);
        }
    }
}

// ---------------- fp32 -> bf16 hi/lo split (activations only) ----------------
__global__ void __launch_bounds__(256) split_kernel(
    const float* __restrict__ in, bf16* __restrict__ hi, bf16* __restrict__ lo, long long n)
{
    long long i = ((long long)blockIdx.x * 256 + threadIdx.x) * 4;
    if (i >= n) return;
    float4 v = *reinterpret_cast<const float4*>(in + i);
    bf16 h0, h1, h2, h3, l0, l1, l2, l3;
    split2(v.x, h0, l0); split2(v.y, h1, l1); split2(v.z, h2, l2); split2(v.w, h3, l3);
    *reinterpret_cast<uint2*>(hi + i) = make_uint2(pk(h0,h1), pk(h2,h3));
    *reinterpret_cast<uint2*>(lo + i) = make_uint2(pk(l0,l1), pk(l2,l3));
}

// ---------------- RMSNorm with fused split ----------------
__global__ void __launch_bounds__(256) rmsnorm_split_kernel(
    const float* __restrict__ x, const float* __restrict__ w,
    bf16* __restrict__ yhi, bf16* __restrict__ ylo)
{
    int s = blockIdx.x;
    const float* rowp = x + (long long)s * HID;
    int tid = threadIdx.x;

    float ss = 0.f;
    for (int i = tid; i < HID; i += 256) { float v = rowp[i]; ss += v * v; }
    __shared__ float red[256];
    red[tid] = ss; __syncthreads();
    for (int st = 128; st > 0; st >>= 1) { if (tid < st) red[tid] += red[tid + st]; __syncthreads(); }
    float inv = rsqrtf(red[0] / (float)HID + 1e-6f);

    bf16* oh = yhi + (long long)s * HID;
    bf16* ol = ylo + (long long)s * HID;
    for (int i = tid; i < HID; i += 256) {
        float v = rowp[i] * inv * w[i];
        bf16 h, l; split2(v, h, l);
        oh[i] = h; ol[i] = l;
    }
}

// ------------ fused residual add + RMSNorm + split (h updated) -------------
__global__ void __launch_bounds__(256) add_rms_split_kernel(
    float* __restrict__ h, const float* __restrict__ o, const float* __restrict__ w,
    bf16* __restrict__ yhi, bf16* __restrict__ ylo)
{
    int s = blockIdx.x;
    long long base = (long long)s * HID;
    int tid = threadIdx.x;
    __shared__ float v[HID];
    __shared__ float red[256];

    float ss = 0.f;
    for (int i = tid; i < HID; i += 256) {
        float t = h[base + i] + o[base + i];
        h[base + i] = t;
        v[i] = t;
        ss += t * t;
    }
    red[tid] = ss; __syncthreads();
    for (int st = 128; st > 0; st >>= 1) { if (tid < st) red[tid] += red[tid + st]; __syncthreads(); }
    float inv = rsqrtf(red[0] / (float)HID + 1e-6f);

    bf16* oh = yhi + base;
    bf16* ol = ylo + base;
    for (int i = tid; i < HID; i += 256) {
        float t = v[i] * inv * w[i];
        bf16 hh, ll; split2(t, hh, ll);
        oh[i] = hh; ol[i] = ll;
    }
}

// -------- RoPE q/k + coalesced V transpose (per head, per 128-s tile) -------
__global__ void __launch_bounds__(256) rope_v_kernel(
    const float* __restrict__ qkv,
    const float* __restrict__ cosT, const float* __restrict__ sinT,
    const int* __restrict__ pos_ids,
    bf16* __restrict__ qhi, bf16* __restrict__ qlo,
    bf16* __restrict__ khi, bf16* __restrict__ klo,
    bf16* __restrict__ vthi, bf16* __restrict__ vtlo)
{
    extern __shared__ uint32_t T[];   // [128][129] packed (hi,lo)
    int head = blockIdx.x;
    int st = blockIdx.y * 128;
    int tid = threadIdx.x;

    for (int i = tid; i < 128 * 128; i += 256) {
        int sl = i >> 7, d = i & 127;
        int s = st + sl;
        int pos = pos_ids[s];
        if (pos < 0) pos = 0;
        if (pos >= SEQ) pos = SEQ - 1;
        const float* rowp = qkv + (long long)s * (3 * HID);
        int idx = head * HD + d;
        float qv = rowp[idx];
        float kv = rowp[HID + idx];
        float vv = rowp[2 * HID + idx];
        float qo = (d < 64) ? -rowp[idx + 64] : rowp[idx - 64];
        float ko = (d < 64) ? -rowp[HID + idx + 64] : rowp[HID + idx - 64];
        float cd = cosT[(long long)pos * HD + d];
        float sd = sinT[(long long)pos * HD + d];
        float qr = qv * cd + qo * sd;
        float kr = kv * cd + ko * sd;
        long long qi = ((long long)head * SEQ + s) * HD + d;
        bf16 hh, ll;
        split2(qr, hh, ll); qhi[qi] = hh; qlo[qi] = ll;
        split2(kr, hh, ll); khi[qi] = hh; klo[qi] = ll;
        split2(vv, hh, ll);
        T[sl * 129 + d] = pk(hh, ll);
    }
    __syncthreads();
    for (int i = tid; i < 128 * 128; i += 256) {
        int d = i >> 7, sl = i & 127;
        uint32_t p = T[sl * 129 + d];
        long long vi = ((long long)head * HD + d) * SEQ + st + sl;
        vthi[vi] = __ushort_as_bfloat16((unsigned short)(p & 0xFFFF));
        vtlo[vi] = __ushort_as_bfloat16((unsigned short)(p >> 16));
    }
}

// ---------------- causal softmax with fused split ----------------
__global__ void __launch_bounds__(256) softmax_split_kernel(
    float* __restrict__ scores, bf16* __restrict__ phi, bf16* __restrict__ plo)
{
    int qrow = blockIdx.x;
    int head = blockIdx.y;
    long long off = ((long long)head * SEQ + qrow) * SEQ;
    float* rowp = scores + off;
    bf16* oh = phi + off;
    bf16* ol = plo + off;
    int n = qrow + 1;
    int tid = threadIdx.x;
    const float scale = 0.088388347648318447f;

    __shared__ float red[256];

    float m = -3.4e38f;
    for (int i = tid; i < n; i += 256) m = fmaxf(m, rowp[i] * scale);
    red[tid] = m; __syncthreads();
    for (int st = 128; st > 0; st >>= 1) { if (tid < st) red[tid] = fmaxf(red[tid], red[tid + st]); __syncthreads(); }
    m = red[0]; __syncthreads();

    float sum = 0.f;
    for (int i = tid; i < n; i += 256) {
        float e = expf(rowp[i] * scale - m);
        rowp[i] = e;
        sum += e;
    }
    red[tid] = sum; __syncthreads();
    for (int st = 128; st > 0; st >>= 1) { if (tid < st) red[tid] += red[tid + st]; __syncthreads(); }
    float inv = 1.f / red[0];

    for (int i = tid; i < n; i += 256) {
        float p = rowp[i] * inv;
        bf16 h, l; split2(p, h, l);
        oh[i] = h; ol[i] = l;
    }
    bf16 z = __float2bfloat16(0.f);
    for (int i = n + tid; i < SEQ; i += 256) { oh[i] = z; ol[i] = z; }
}

// ---------------- elementwise ----------------
__global__ void __launch_bounds__(256) add_kernel(float* __restrict__ a, const float* __restrict__ b, int n)
{
    int i = blockIdx.x * 256 + threadIdx.x;
    if (i < n) a[i] += b[i];
}

__global__ void __launch_bounds__(256) silu_mul_split_kernel(
    const float* __restrict__ f, bf16* __restrict__ ghi, bf16* __restrict__ glo, int n)
{
    int i = blockIdx.x * 256 + threadIdx.x;
    if (i < n) {
        int s = i / INTER, c = i - s * INTER;
        long long base = (long long)s * (2 * INTER);
        float x = f[base + c];
        float v = x / (1.f + expf(-x)) * f[base + INTER + c];
        bf16 h, l; split2(v, h, l);
        ghi[i] = h; glo[i] = l;
    }
}

// ---------------- orchestration ----------------
static inline void launch_gemm_w(const bf16* Ahi, const bf16* Alo,
                                 const float* B1, const float* B2, int N1, float* C,
                                 int M, int N, int K, int lda, int ldb, int ldc)
{
    dim3 grid(M / 256, N / 128);
    gemm_wsplit<<<grid, 256, SMEM_SZ>>>(Ahi, Alo, B1, B2, N1, C, K, lda, ldb, ldc);
}

static inline void launch_gemm_a(const bf16* Ahi, const bf16* Alo,
                                 const bf16* Bhi, const bf16* Blo, float* C,
                                 int M, int N, int K, int lda, int ldb, int ldc,
                                 long long sA, long long sB, long long sC, int batch, int mode)
{
    dim3 grid(M / 256, N / 128, batch);
    gemm_bf16_split<<<grid, 256, SMEM_SZ>>>(Ahi, Alo, Bhi, Blo, C, K, lda, ldb, ldc, sA, sB, sC, mode);
}

extern "C" void kernel_launch(void* const* d_in, const int* in_sizes, int n_in,
                              void* d_out, int out_size)
{
    const float* x      = (const float*)d_in[0];
    const int*   pos    = (const int*)d_in[1];
    const float* qkv_w  = (const float*)d_in[2];
    const float* o_w    = (const float*)d_in[3];
    const float* gate_w = (const float*)d_in[4];
    const float* up_w   = (const float*)d_in[5];
    const float* down_w = (const float*)d_in[6];
    const float* ln1_w  = (const float*)d_in[7];
    const float* ln2_w  = (const float*)d_in[8];
    const float* cosT   = (const float*)d_in[9];
    const float* sinT   = (const float*)d_in[10];
    float* h = (float*)d_out;

    cudaFuncSetAttribute(gemm_wsplit, cudaFuncAttributeMaxDynamicSharedMemorySize, SMEM_SZ);
    cudaFuncSetAttribute(gemm_bf16_split, cudaFuncAttributeMaxDynamicSharedMemorySize, SMEM_SZ);
    cudaFuncSetAttribute(rope_v_kernel, cudaFuncAttributeMaxDynamicSharedMemorySize, 128 * 129 * 4);

    float *y, *o, *qkv, *sc, *f;
    bf16 *yhi, *ylo, *qhi, *qlo, *khi, *klo, *vthi, *vtlo, *phi, *plo, *ghi, *glo;
    cudaGetSymbolAddress((void**)&y, g_y);
    cudaGetSymbolAddress((void**)&o, g_o);
    cudaGetSymbolAddress((void**)&qkv, g_qkv);
    cudaGetSymbolAddress((void**)&sc, g_sc);
    cudaGetSymbolAddress((void**)&f, g_f);
    cudaGetSymbolAddress((void**)&yhi, g_yhi);
    cudaGetSymbolAddress((void**)&ylo, g_ylo);
    cudaGetSymbolAddress((void**)&qhi, g_qhi);
    cudaGetSymbolAddress((void**)&qlo, g_qlo);
    cudaGetSymbolAddress((void**)&khi, g_khi);
    cudaGetSymbolAddress((void**)&klo, g_klo);
    cudaGetSymbolAddress((void**)&vthi, g_vthi);
    cudaGetSymbolAddress((void**)&vtlo, g_vtlo);
    cudaGetSymbolAddress((void**)&phi, g_phi);
    cudaGetSymbolAddress((void**)&plo, g_plo);
    cudaGetSymbolAddress((void**)&ghi, g_ghi);
    cudaGetSymbolAddress((void**)&glo, g_glo);

    cudaMemcpyAsync(h, x, sizeof(float) * SEQ * HID, cudaMemcpyDeviceToDevice, 0);

    const int nEl = SEQ * HID;
    const int nElI = SEQ * INTER;
    const int BIGN = 1 << 30;

    rmsnorm_split_kernel<<<SEQ, 256>>>(h, ln1_w, yhi, ylo);

    for (int L = 0; L < NL; L++) {
        const float* qw = qkv_w  + (size_t)L * 3 * HID * HID;
        const float* ow = o_w    + (size_t)L * HID * HID;
        const float* gw = gate_w + (size_t)L * INTER * HID;
        const float* uw = up_w   + (size_t)L * INTER * HID;
        const float* dw = down_w + (size_t)L * HID * INTER;

        // ---- attention ----
        launch_gemm_w(yhi, ylo, qw, qw, BIGN, qkv, SEQ, 3 * HID, HID, HID, HID, 3 * HID);

        rope_v_kernel<<<dim3(NH, SEQ / 128), 256, 128 * 129 * 4>>>(
            qkv, cosT, sinT, pos, qhi, qlo, khi, klo, vthi, vtlo);

        launch_gemm_a(qhi, qlo, khi, klo, sc, SEQ, SEQ, HD, HD, HD, SEQ,
                      (long long)SEQ * HD, (long long)SEQ * HD, (long long)SEQ * SEQ, NH, 1);

        softmax_split_kernel<<<dim3(SEQ, NH), 256>>>(sc, phi, plo);

        launch_gemm_a(phi, plo, vthi, vtlo, y, SEQ, HD, SEQ, SEQ, SEQ, HID,
                      (long long)SEQ * SEQ, (long long)HD * SEQ, (long long)HD, NH, 2);

        { long long n = nEl; split_kernel<<<(int)((n / 4 + 255) / 256), 256>>>(y, yhi, ylo, n); }

        launch_gemm_w(yhi, ylo, ow, ow, BIGN, o, SEQ, HID, HID, HID, HID, HID);

        add_rms_split_kernel<<<SEQ, 256>>>(h, o, ln2_w + (size_t)L * HID, yhi, ylo);

        // ---- MLP: fused gate|up ----
        launch_gemm_w(yhi, ylo, gw, uw, INTER, f, SEQ, 2 * INTER, HID, HID, HID, 2 * INTER);

        silu_mul_split_kernel<<<nElI / 256, 256>>>(f, ghi, glo, nElI);

        launch_gemm_w(ghi, glo, dw, dw, BIGN, o, SEQ, HID, INTER, INTER, INTER, HID);

        if (L < NL - 1) {
            add_rms_split_kernel<<<SEQ, 256>>>(h, o, ln1_w + (size_t)(L + 1) * HID, yhi, ylo);
        } else {
            add_kernel<<<nEl / 256, 256>>>(h, o, nEl);
        }
    }
}

// round 10
// speedup vs baseline: 3.1474x; 1.0682x over previous
#include <cuda_runtime.h>
#include <cuda_bf16.h>
#include <math.h>
#include <stdint.h>

#define SEQ   1024
#define HID   4096
#define NH    32
#define HD    128
#define INTER 11008
#define NL    2

typedef __nv_bfloat16 bf16;

// ---------------- scratch (device globals; no allocations allowed) ----------
__device__ float g_y[SEQ * HID];
__device__ float g_o[SEQ * HID];
__device__ float g_qkv[SEQ * 3 * HID];
__device__ float g_sc[(size_t)NH * SEQ * SEQ];
__device__ float g_f[(size_t)SEQ * 2 * INTER];     // fused gate|up output

__device__ bf16 g_yhi[SEQ * HID],  g_ylo[SEQ * HID];
__device__ bf16 g_qhi[SEQ * HID],  g_qlo[SEQ * HID];
__device__ bf16 g_khi[SEQ * HID],  g_klo[SEQ * HID];
__device__ bf16 g_vthi[SEQ * HID], g_vtlo[SEQ * HID];
__device__ bf16 g_phi[(size_t)NH * SEQ * SEQ], g_plo[(size_t)NH * SEQ * SEQ];
__device__ bf16 g_ghi[SEQ * INTER], g_glo[SEQ * INTER];

// ======================= helpers ==============================
__device__ __forceinline__ uint32_t smem_u32(const void* p) {
    uint32_t a;
    asm("{ .reg .u64 t; cvta.to.shared.u64 t, %1; cvt.u32.u64 %0, t; }" : "=r"(a) : "l"(p));
    return a;
}

__device__ __forceinline__ void ldsm_x4(uint32_t* r, uint32_t addr) {
    asm volatile("ldmatrix.sync.aligned.m8n8.x4.shared.b16 {%0,%1,%2,%3}, [%4];"
                 : "=r"(r[0]), "=r"(r[1]), "=r"(r[2]), "=r"(r[3]) : "r"(addr));
}

__device__ __forceinline__ void mma_bf16(float* c, const uint32_t* a, uint32_t b0, uint32_t b1) {
    asm volatile(
        "mma.sync.aligned.m16n8k16.row.col.f32.bf16.bf16.f32 "
        "{%0,%1,%2,%3}, {%4,%5,%6,%7}, {%8,%9}, {%0,%1,%2,%3};"
        : "+f"(c[0]), "+f"(c[1]), "+f"(c[2]), "+f"(c[3])
        : "r"(a[0]), "r"(a[1]), "r"(a[2]), "r"(a[3]), "r"(b0), "r"(b1));
}

#define CP16(dst, src) asm volatile("cp.async.cg.shared.global [%0], [%1], 16;" :: "r"(dst), "l"(src))
#define CP_COMMIT()    asm volatile("cp.async.commit_group;" ::: "memory")
#define CP_WAIT1()     asm volatile("cp.async.wait_group 1;" ::: "memory")

__device__ __forceinline__ void split2(float x, bf16& h, bf16& l) {
    h = __float2bfloat16(x);
    l = __float2bfloat16(x - __bfloat162float(h));
}

__device__ __forceinline__ uint32_t pk(bf16 a, bf16 b) {
    return (uint32_t)__bfloat16_as_ushort(a) | ((uint32_t)__bfloat16_as_ushort(b) << 16);
}

// ==================== shared tile geometry ====================
// CTA tile 256x128, 512 threads (16 warps, 4x4), warp tile 64x32, Kc=32.
#define NT    512
#define ROWB   80
#define ATILE  (256 * ROWB)              // 20480 B
#define BTILE  (128 * ROWB)              // 10240 B
#define STAGEB (2 * ATILE + 2 * BTILE)   // 61440 B
#define STAGES 3
#define SMEM_SZ (STAGES * STAGEB)        // 184320 B

// A (bf16 hi/lo) stage loader via cp.async (512 threads)
__device__ __forceinline__ void a_stage_load(
    uint32_t sdst, const bf16* __restrict__ Ahi, const bf16* __restrict__ Alo,
    int lda, int k0, int bm, int tid)
{
    #pragma unroll
    for (int i = 0; i < 2; i++) {
        int idx = tid + i * NT;
        int r = idx >> 2, seg = (idx & 3) * 8;
        uint32_t so = sdst + (uint32_t)r * ROWB + (uint32_t)seg * 2;
        long long g = (long long)(bm + r) * lda + k0 + seg;
        CP16(so,         Ahi + g);
        CP16(so + ATILE, Alo + g);
    }
}

// term-major MMA block for one mt: 4x hh, 4x lh, 4x hl
#define MMA_TERM_MAJOR(accmt, ah, al, bh, bl)                                   \
    do {                                                                        \
        _Pragma("unroll")                                                       \
        for (int nt = 0; nt < 4; nt++)                                          \
            mma_bf16((accmt)[nt], ah, bh[nt >> 1][(nt & 1) * 2],                \
                     bh[nt >> 1][(nt & 1) * 2 + 1]);                            \
        _Pragma("unroll")                                                       \
        for (int nt = 0; nt < 4; nt++)                                          \
            mma_bf16((accmt)[nt], al, bh[nt >> 1][(nt & 1) * 2],                \
                     bh[nt >> 1][(nt & 1) * 2 + 1]);                            \
        _Pragma("unroll")                                                       \
        for (int nt = 0; nt < 4; nt++)                                          \
            mma_bf16((accmt)[nt], ah, bl[nt >> 1][(nt & 1) * 2],                \
                     bl[nt >> 1][(nt & 1) * 2 + 1]);                            \
    } while (0)

// ============ GEMM 1: A bf16 hi/lo  ×  B fp32 weights (in-kernel split) ======
__global__ void __launch_bounds__(NT, 1)
gemm_wsplit(const bf16* __restrict__ Ahi, const bf16* __restrict__ Alo,
            const float* __restrict__ B1, const float* __restrict__ B2, int N1,
            float* __restrict__ C, int K, int lda, int ldb, int ldc)
{
    extern __shared__ char smem[];
    const int tid = threadIdx.x;
    const int lane = tid & 31;
    const int wid = tid >> 5;
    const int wm = wid & 3;           // 0..3 (64-row quadrant)
    const int wn = wid >> 2;          // 0..3 (32-col quarter)

    const int bm = blockIdx.x * 256;
    const int bn = blockIdx.y * 128;

    const float* W = (bn < N1) ? (B1 + (long long)bn * ldb)
                               : (B2 + (long long)(bn - N1) * ldb);

    const uint32_t sb = smem_u32(smem);
    const int nk = K / 32;

    // B loader: 4 threads per row, 8 fp32 each
    const int br = tid >> 2;
    const int bc = (tid & 3) * 8;
    const float* Wrow = W + (long long)br * ldb + bc;
    const uint32_t bsts = (uint32_t)br * ROWB + (uint32_t)bc * 2;

    const uint32_t aOff = (uint32_t)(wm * 64 + (lane & 15)) * ROWB + (uint32_t)(lane >> 4) * 16;
    const uint32_t bOff = (uint32_t)(wn * 32 + (((lane >> 4) << 3) | (lane & 7))) * ROWB
                        + (uint32_t)((lane >> 3) & 1) * 16;

    float acc[4][4][4];
    #pragma unroll
    for (int mt = 0; mt < 4; mt++)
        #pragma unroll
        for (int nt = 0; nt < 4; nt++)
            #pragma unroll
            for (int i = 0; i < 4; i++) acc[mt][nt][i] = 0.f;

    float4 rB[2];

    // ---- prologue ----
    rB[0] = *reinterpret_cast<const float4*>(Wrow);
    rB[1] = *reinterpret_cast<const float4*>(Wrow + 4);
    {
        bf16 h0,h1,h2,h3,l0,l1,l2,l3;
        #pragma unroll
        for (int v = 0; v < 2; v++) {
            split2(rB[v].x, h0, l0); split2(rB[v].y, h1, l1);
            split2(rB[v].z, h2, l2); split2(rB[v].w, h3, l3);
            *reinterpret_cast<uint2*>(smem + 2 * ATILE + bsts + v * 8) = make_uint2(pk(h0,h1), pk(h2,h3));
            *reinterpret_cast<uint2*>(smem + 2 * ATILE + BTILE + bsts + v * 8) = make_uint2(pk(l0,l1), pk(l2,l3));
        }
    }
    a_stage_load(sb, Ahi, Alo, lda, 0, bm, tid);
    CP_COMMIT();
    if (nk > 1) a_stage_load(sb + STAGEB, Ahi, Alo, lda, 32, bm, tid);
    CP_COMMIT();
    if (nk > 1) {
        rB[0] = *reinterpret_cast<const float4*>(Wrow + 32);
        rB[1] = *reinterpret_cast<const float4*>(Wrow + 36);
    }

    for (int j = 0; j < nk; j++) {
        CP_WAIT1();
        __syncthreads();

        int jn = j + 2;
        if (jn < nk)
            a_stage_load(sb + (uint32_t)(jn % STAGES) * STAGEB, Ahi, Alo, lda, jn * 32, bm, tid);
        CP_COMMIT();

        const uint32_t st = sb + (uint32_t)(j % STAGES) * STAGEB;
        #pragma unroll
        for (int kk = 0; kk < 2; kk++) {
            uint32_t bh[2][4], bl[2][4];
            #pragma unroll
            for (int n2 = 0; n2 < 2; n2++) {
                uint32_t base = st + bOff + 2 * ATILE + (uint32_t)n2 * (16 * ROWB) + (uint32_t)kk * 32;
                ldsm_x4(bh[n2], base);
                ldsm_x4(bl[n2], base + BTILE);
            }
            #pragma unroll
            for (int mt = 0; mt < 4; mt++) {
                uint32_t ah[4], al[4];
                uint32_t base = st + aOff + (uint32_t)mt * (16 * ROWB) + (uint32_t)kk * 32;
                ldsm_x4(ah, base);
                ldsm_x4(al, base + ATILE);
                MMA_TERM_MAJOR(acc[mt], ah, al, bh, bl);
            }
        }

        if (j + 1 < nk) {
            uint32_t dst = (uint32_t)((j + 1) % STAGES) * STAGEB + 2 * ATILE + bsts;
            bf16 h0,h1,h2,h3,l0,l1,l2,l3;
            #pragma unroll
            for (int v = 0; v < 2; v++) {
                split2(rB[v].x, h0, l0); split2(rB[v].y, h1, l1);
                split2(rB[v].z, h2, l2); split2(rB[v].w, h3, l3);
                *reinterpret_cast<uint2*>(smem + dst + v * 8) = make_uint2(pk(h0,h1), pk(h2,h3));
                *reinterpret_cast<uint2*>(smem + dst + BTILE + v * 8) = make_uint2(pk(l0,l1), pk(l2,l3));
            }
        }
        if (j + 2 < nk) {
            const float* p = Wrow + (j + 2) * 32;
            rB[0] = *reinterpret_cast<const float4*>(p);
            rB[1] = *reinterpret_cast<const float4*>(p + 4);
        }
    }

    const int gr = lane >> 2;
    const int gc = (lane & 3) * 2;
    #pragma unroll
    for (int mt = 0; mt < 4; mt++) {
        int row0 = bm + wm * 64 + mt * 16 + gr;
        #pragma unroll
        for (int nt = 0; nt < 4; nt++) {
            int c = bn + wn * 32 + nt * 8 + gc;
            *reinterpret_cast<float2*>(C + (long long)row0 * ldc + c) =
                make_float2(acc[mt][nt][0], acc[mt][nt][1]);
            *reinterpret_cast<float2*>(C + (long long)(row0 + 8) * ldc + c) =
                make_float2(acc[mt][nt][2], acc[mt][nt][3]);
        }
    }
}

// ============ GEMM 2: both operands bf16 hi/lo (attention) ==================
__device__ __forceinline__ void stage_load_ab(
    uint32_t sdst,
    const bf16* __restrict__ Ahi, const bf16* __restrict__ Alo,
    const bf16* __restrict__ Bhi, const bf16* __restrict__ Blo,
    int lda, int ldb, int k0, int bm, int bn, int tid)
{
    #pragma unroll
    for (int i = 0; i < 2; i++) {
        int idx = tid + i * NT;
        int r = idx >> 2, seg = (idx & 3) * 8;
        uint32_t so = sdst + (uint32_t)r * ROWB + (uint32_t)seg * 2;
        long long g = (long long)(bm + r) * lda + k0 + seg;
        CP16(so,         Ahi + g);
        CP16(so + ATILE, Alo + g);
    }
    {
        int r = tid >> 2, seg = (tid & 3) * 8;
        uint32_t so = sdst + 2 * ATILE + (uint32_t)r * ROWB + (uint32_t)seg * 2;
        long long g = (long long)(bn + r) * ldb + k0 + seg;
        CP16(so,         Bhi + g);
        CP16(so + BTILE, Blo + g);
    }
}

__global__ void __launch_bounds__(NT, 1)
gemm_bf16_split(const bf16* __restrict__ Ahi, const bf16* __restrict__ Alo,
                const bf16* __restrict__ Bhi, const bf16* __restrict__ Blo,
                float* __restrict__ C, int K, int lda, int ldb, int ldc,
                long long sA, long long sB, long long sC, int mode)
{
    extern __shared__ char smem[];
    const int tid = threadIdx.x;
    const int lane = tid & 31;
    const int wid = tid >> 5;
    const int wm = wid & 3;
    const int wn = wid >> 2;

    const int bm = blockIdx.x * 256;
    const int bn = blockIdx.y * 128;
    if (mode == 1 && bn >= bm + 256) return;

    Ahi += (long long)blockIdx.z * sA;
    Alo += (long long)blockIdx.z * sA;
    Bhi += (long long)blockIdx.z * sB;
    Blo += (long long)blockIdx.z * sB;
    C   += (long long)blockIdx.z * sC;

    int kend = (mode == 2) ? min(K, bm + 256) : K;
    const int nk = kend / 32;

    const uint32_t sb = smem_u32(smem);

    const uint32_t aOff = (uint32_t)(wm * 64 + (lane & 15)) * ROWB + (uint32_t)(lane >> 4) * 16;
    const uint32_t bOff = (uint32_t)(wn * 32 + (((lane >> 4) << 3) | (lane & 7))) * ROWB
                        + (uint32_t)((lane >> 3) & 1) * 16;

    float acc[4][4][4];
    #pragma unroll
    for (int mt = 0; mt < 4; mt++)
        #pragma unroll
        for (int nt = 0; nt < 4; nt++)
            #pragma unroll
            for (int i = 0; i < 4; i++) acc[mt][nt][i] = 0.f;

    #pragma unroll
    for (int j = 0; j < STAGES - 1; j++) {
        if (j < nk)
            stage_load_ab(sb + (uint32_t)(j % STAGES) * STAGEB,
                          Ahi, Alo, Bhi, Blo, lda, ldb, j * 32, bm, bn, tid);
        CP_COMMIT();
    }

    for (int j = 0; j < nk; j++) {
        CP_WAIT1();
        __syncthreads();

        int jn = j + STAGES - 1;
        if (jn < nk)
            stage_load_ab(sb + (uint32_t)(jn % STAGES) * STAGEB,
                          Ahi, Alo, Bhi, Blo, lda, ldb, jn * 32, bm, bn, tid);
        CP_COMMIT();

        const uint32_t st = sb + (uint32_t)(j % STAGES) * STAGEB;
        #pragma unroll
        for (int kk = 0; kk < 2; kk++) {
            uint32_t bh[2][4], bl[2][4];
            #pragma unroll
            for (int n2 = 0; n2 < 2; n2++) {
                uint32_t base = st + bOff + 2 * ATILE + (uint32_t)n2 * (16 * ROWB) + (uint32_t)kk * 32;
                ldsm_x4(bh[n2], base);
                ldsm_x4(bl[n2], base + BTILE);
            }
            #pragma unroll
            for (int mt = 0; mt < 4; mt++) {
                uint32_t ah[4], al[4];
                uint32_t base = st + aOff + (uint32_t)mt * (16 * ROWB) + (uint32_t)kk * 32;
                ldsm_x4(ah, base);
                ldsm_x4(al, base + ATILE);
                MMA_TERM_MAJOR(acc[mt], ah, al, bh, bl);
            }
        }
    }

    const int gr = lane >> 2;
    const int gc = (lane & 3) * 2;
    #pragma unroll
    for (int mt = 0; mt < 4; mt++) {
        int row0 = bm + wm * 64 + mt * 16 + gr;
        #pragma unroll
        for (int nt = 0; nt < 4; nt++) {
            int c = bn + wn * 32 + nt * 8 + gc;
            *reinterpret_cast<float2*>(C + (long long)row0 * ldc + c) =
                make_float2(acc[mt][nt][0], acc[mt][nt][1]);
            *reinterpret_cast<float2*>(C + (long long)(row0 + 8) * ldc + c) =
                make_float2(acc[mt][nt][2], acc[mt][nt][3]);
        }
    }
}

// ---------------- fp32 -> bf16 hi/lo split (activations only) ----------------
__global__ void __launch_bounds__(256) split_kernel(
    const float* __restrict__ in, bf16* __restrict__ hi, bf16* __restrict__ lo, long long n)
{
    long long i = ((long long)blockIdx.x * 256 + threadIdx.x) * 4;
    if (i >= n) return;
    float4 v = *reinterpret_cast<const float4*>(in + i);
    bf16 h0, h1, h2, h3, l0, l1, l2, l3;
    split2(v.x, h0, l0); split2(v.y, h1, l1); split2(v.z, h2, l2); split2(v.w, h3, l3);
    *reinterpret_cast<uint2*>(hi + i) = make_uint2(pk(h0,h1), pk(h2,h3));
    *reinterpret_cast<uint2*>(lo + i) = make_uint2(pk(l0,l1), pk(l2,l3));
}

// ---------------- RMSNorm with fused split ----------------
__global__ void __launch_bounds__(256) rmsnorm_split_kernel(
    const float* __restrict__ x, const float* __restrict__ w,
    bf16* __restrict__ yhi, bf16* __restrict__ ylo)
{
    int s = blockIdx.x;
    const float* rowp = x + (long long)s * HID;
    int tid = threadIdx.x;

    float ss = 0.f;
    for (int i = tid; i < HID; i += 256) { float v = rowp[i]; ss += v * v; }
    __shared__ float red[256];
    red[tid] = ss; __syncthreads();
    for (int st = 128; st > 0; st >>= 1) { if (tid < st) red[tid] += red[tid + st]; __syncthreads(); }
    float inv = rsqrtf(red[0] / (float)HID + 1e-6f);

    bf16* oh = yhi + (long long)s * HID;
    bf16* ol = ylo + (long long)s * HID;
    for (int i = tid; i < HID; i += 256) {
        float v = rowp[i] * inv * w[i];
        bf16 h, l; split2(v, h, l);
        oh[i] = h; ol[i] = l;
    }
}

// ------------ fused residual add + RMSNorm + split (h updated) -------------
__global__ void __launch_bounds__(256) add_rms_split_kernel(
    float* __restrict__ h, const float* __restrict__ o, const float* __restrict__ w,
    bf16* __restrict__ yhi, bf16* __restrict__ ylo)
{
    int s = blockIdx.x;
    long long base = (long long)s * HID;
    int tid = threadIdx.x;
    __shared__ float v[HID];
    __shared__ float red[256];

    float ss = 0.f;
    for (int i = tid; i < HID; i += 256) {
        float t = h[base + i] + o[base + i];
        h[base + i] = t;
        v[i] = t;
        ss += t * t;
    }
    red[tid] = ss; __syncthreads();
    for (int st = 128; st > 0; st >>= 1) { if (tid < st) red[tid] += red[tid + st]; __syncthreads(); }
    float inv = rsqrtf(red[0] / (float)HID + 1e-6f);

    bf16* oh = yhi + base;
    bf16* ol = ylo + base;
    for (int i = tid; i < HID; i += 256) {
        float t = v[i] * inv * w[i];
        bf16 hh, ll; split2(t, hh, ll);
        oh[i] = hh; ol[i] = ll;
    }
}

// -------- RoPE q/k + coalesced V transpose (per head, per 128-s tile) -------
__global__ void __launch_bounds__(256) rope_v_kernel(
    const float* __restrict__ qkv,
    const float* __restrict__ cosT, const float* __restrict__ sinT,
    const int* __restrict__ pos_ids,
    bf16* __restrict__ qhi, bf16* __restrict__ qlo,
    bf16* __restrict__ khi, bf16* __restrict__ klo,
    bf16* __restrict__ vthi, bf16* __restrict__ vtlo)
{
    extern __shared__ uint32_t T[];   // [128][129] packed (hi,lo)
    int head = blockIdx.x;
    int st = blockIdx.y * 128;
    int tid = threadIdx.x;

    for (int i = tid; i < 128 * 128; i += 256) {
        int sl = i >> 7, d = i & 127;
        int s = st + sl;
        int pos = pos_ids[s];
        if (pos < 0) pos = 0;
        if (pos >= SEQ) pos = SEQ - 1;
        const float* rowp = qkv + (long long)s * (3 * HID);
        int idx = head * HD + d;
        float qv = rowp[idx];
        float kv = rowp[HID + idx];
        float vv = rowp[2 * HID + idx];
        float qo = (d < 64) ? -rowp[idx + 64] : rowp[idx - 64];
        float ko = (d < 64) ? -rowp[HID + idx + 64] : rowp[HID + idx - 64];
        float cd = cosT[(long long)pos * HD + d];
        float sd = sinT[(long long)pos * HD + d];
        float qr = qv * cd + qo * sd;
        float kr = kv * cd + ko * sd;
        long long qi = ((long long)head * SEQ + s) * HD + d;
        bf16 hh, ll;
        split2(qr, hh, ll); qhi[qi] = hh; qlo[qi] = ll;
        split2(kr, hh, ll); khi[qi] = hh; klo[qi] = ll;
        split2(vv, hh, ll);
        T[sl * 129 + d] = pk(hh, ll);
    }
    __syncthreads();
    for (int i = tid; i < 128 * 128; i += 256) {
        int d = i >> 7, sl = i & 127;
        uint32_t p = T[sl * 129 + d];
        long long vi = ((long long)head * HD + d) * SEQ + st + sl;
        vthi[vi] = __ushort_as_bfloat16((unsigned short)(p & 0xFFFF));
        vtlo[vi] = __ushort_as_bfloat16((unsigned short)(p >> 16));
    }
}

// ---------------- causal softmax with fused split ----------------
__global__ void __launch_bounds__(256) softmax_split_kernel(
    float* __restrict__ scores, bf16* __restrict__ phi, bf16* __restrict__ plo)
{
    int qrow = blockIdx.x;
    int head = blockIdx.y;
    long long off = ((long long)head * SEQ + qrow) * SEQ;
    float* rowp = scores + off;
    bf16* oh = phi + off;
    bf16* ol = plo + off;
    int n = qrow + 1;
    int tid = threadIdx.x;
    const float scale = 0.088388347648318447f;

    __shared__ float red[256];

    float m = -3.4e38f;
    for (int i = tid; i < n; i += 256) m = fmaxf(m, rowp[i] * scale);
    red[tid] = m; __syncthreads();
    for (int st = 128; st > 0; st >>= 1) { if (tid < st) red[tid] = fmaxf(red[tid], red[tid + st]); __syncthreads(); }
    m = red[0]; __syncthreads();

    float sum = 0.f;
    for (int i = tid; i < n; i += 256) {
        float e = expf(rowp[i] * scale - m);
        rowp[i] = e;
        sum += e;
    }
    red[tid] = sum; __syncthreads();
    for (int st = 128; st > 0; st >>= 1) { if (tid < st) red[tid] += red[tid + st]; __syncthreads(); }
    float inv = 1.f / red[0];

    for (int i = tid; i < n; i += 256) {
        float p = rowp[i] * inv;
        bf16 h, l; split2(p, h, l);
        oh[i] = h; ol[i] = l;
    }
    bf16 z = __float2bfloat16(0.f);
    for (int i = n + tid; i < SEQ; i += 256) { oh[i] = z; ol[i] = z; }
}

// ---------------- elementwise ----------------
__global__ void __launch_bounds__(256) add_kernel(float* __restrict__ a, const float* __restrict__ b, int n)
{
    int i = blockIdx.x * 256 + threadIdx.x;
    if (i < n) a[i] += b[i];
}

__global__ void __launch_bounds__(256) silu_mul_split_kernel(
    const float* __restrict__ f, bf16* __restrict__ ghi, bf16* __restrict__ glo, int n)
{
    int i = blockIdx.x * 256 + threadIdx.x;
    if (i < n) {
        int s = i / INTER, c = i - s * INTER;
        long long base = (long long)s * (2 * INTER);
        float x = f[base + c];
        float v = x / (1.f + expf(-x)) * f[base + INTER + c];
        bf16 h, l; split2(v, h, l);
        ghi[i] = h; glo[i] = l;
    }
}

// ---------------- orchestration ----------------
static inline void launch_gemm_w(const bf16* Ahi, const bf16* Alo,
                                 const float* B1, const float* B2, int N1, float* C,
                                 int M, int N, int K, int lda, int ldb, int ldc)
{
    dim3 grid(M / 256, N / 128);
    gemm_wsplit<<<grid, NT, SMEM_SZ>>>(Ahi, Alo, B1, B2, N1, C, K, lda, ldb, ldc);
}

static inline void launch_gemm_a(const bf16* Ahi, const bf16* Alo,
                                 const bf16* Bhi, const bf16* Blo, float* C,
                                 int M, int N, int K, int lda, int ldb, int ldc,
                                 long long sA, long long sB, long long sC, int batch, int mode)
{
    dim3 grid(M / 256, N / 128, batch);
    gemm_bf16_split<<<grid, NT, SMEM_SZ>>>(Ahi, Alo, Bhi, Blo, C, K, lda, ldb, ldc, sA, sB, sC, mode);
}

extern "C" void kernel_launch(void* const* d_in, const int* in_sizes, int n_in,
                              void* d_out, int out_size)
{
    const float* x      = (const float*)d_in[0];
    const int*   pos    = (const int*)d_in[1];
    const float* qkv_w  = (const float*)d_in[2];
    const float* o_w    = (const float*)d_in[3];
    const float* gate_w = (const float*)d_in[4];
    const float* up_w   = (const float*)d_in[5];
    const float* down_w = (const float*)d_in[6];
    const float* ln1_w  = (const float*)d_in[7];
    const float* ln2_w  = (const float*)d_in[8];
    const float* cosT   = (const float*)d_in[9];
    const float* sinT   = (const float*)d_in[10];
    float* h = (float*)d_out;

    cudaFuncSetAttribute(gemm_wsplit, cudaFuncAttributeMaxDynamicSharedMemorySize, SMEM_SZ);
    cudaFuncSetAttribute(gemm_bf16_split, cudaFuncAttributeMaxDynamicSharedMemorySize, SMEM_SZ);
    cudaFuncSetAttribute(rope_v_kernel, cudaFuncAttributeMaxDynamicSharedMemorySize, 128 * 129 * 4);

    float *y, *o, *qkv, *sc, *f;
    bf16 *yhi, *ylo, *qhi, *qlo, *khi, *klo, *vthi, *vtlo, *phi, *plo, *ghi, *glo;
    cudaGetSymbolAddress((void**)&y, g_y);
    cudaGetSymbolAddress((void**)&o, g_o);
    cudaGetSymbolAddress((void**)&qkv, g_qkv);
    cudaGetSymbolAddress((void**)&sc, g_sc);
    cudaGetSymbolAddress((void**)&f, g_f);
    cudaGetSymbolAddress((void**)&yhi, g_yhi);
    cudaGetSymbolAddress((void**)&ylo, g_ylo);
    cudaGetSymbolAddress((void**)&qhi, g_qhi);
    cudaGetSymbolAddress((void**)&qlo, g_qlo);
    cudaGetSymbolAddress((void**)&khi, g_khi);
    cudaGetSymbolAddress((void**)&klo, g_klo);
    cudaGetSymbolAddress((void**)&vthi, g_vthi);
    cudaGetSymbolAddress((void**)&vtlo, g_vtlo);
    cudaGetSymbolAddress((void**)&phi, g_phi);
    cudaGetSymbolAddress((void**)&plo, g_plo);
    cudaGetSymbolAddress((void**)&ghi, g_ghi);
    cudaGetSymbolAddress((void**)&glo, g_glo);

    cudaMemcpyAsync(h, x, sizeof(float) * SEQ * HID, cudaMemcpyDeviceToDevice, 0);

    const int nEl = SEQ * HID;
    const int nElI = SEQ * INTER;
    const int BIGN = 1 << 30;

    rmsnorm_split_kernel<<<SEQ, 256>>>(h, ln1_w, yhi, ylo);

    for (int L = 0; L < NL; L++) {
        const float* qw = qkv_w  + (size_t)L * 3 * HID * HID;
        const float* ow = o_w    + (size_t)L * HID * HID;
        const float* gw = gate_w + (size_t)L * INTER * HID;
        const float* uw = up_w   + (size_t)L * INTER * HID;
        const float* dw = down_w + (size_t)L * HID * INTER;

        // ---- attention ----
        launch_gemm_w(yhi, ylo, qw, qw, BIGN, qkv, SEQ, 3 * HID, HID, HID, HID, 3 * HID);

        rope_v_kernel<<<dim3(NH, SEQ / 128), 256, 128 * 129 * 4>>>(
            qkv, cosT, sinT, pos, qhi, qlo, khi, klo, vthi, vtlo);

        launch_gemm_a(qhi, qlo, khi, klo, sc, SEQ, SEQ, HD, HD, HD, SEQ,
                      (long long)SEQ * HD, (long long)SEQ * HD, (long long)SEQ * SEQ, NH, 1);

        softmax_split_kernel<<<dim3(SEQ, NH), 256>>>(sc, phi, plo);

        launch_gemm_a(phi, plo, vthi, vtlo, y, SEQ, HD, SEQ, SEQ, SEQ, HID,
                      (long long)SEQ * SEQ, (long long)HD * SEQ, (long long)HD, NH, 2);

        { long long n = nEl; split_kernel<<<(int)((n / 4 + 255) / 256), 256>>>(y, yhi, ylo, n); }

        launch_gemm_w(yhi, ylo, ow, ow, BIGN, o, SEQ, HID, HID, HID, HID, HID);

        add_rms_split_kernel<<<SEQ, 256>>>(h, o, ln2_w + (size_t)L * HID, yhi, ylo);

        // ---- MLP: fused gate|up ----
        launch_gemm_w(yhi, ylo, gw, uw, INTER, f, SEQ, 2 * INTER, HID, HID, HID, 2 * INTER);

        silu_mul_split_kernel<<<nElI / 256, 256>>>(f, ghi, glo, nElI);

        launch_gemm_w(ghi, glo, dw, dw, BIGN, o, SEQ, HID, INTER, INTER, INTER, HID);

        if (L < NL - 1) {
            add_rms_split_kernel<<<SEQ, 256>>>(h, o, ln1_w + (size_t)(L + 1) * HID, yhi, ylo);
        } else {
            add_kernel<<<nEl / 256, 256>>>(h, o, nEl);
        }
    }
}